// round 3
// baseline (speedup 1.0000x reference)
#include <cuda_runtime.h>

#define HW 65536
#define IMW 256

// ------------------------- device scratch (no allocations) -------------------------
static __device__ float g_projT[128*128];
static __device__ float g_preT [64*64];
static __device__ float g_qkvT [64*192];
static __device__ float g_g1T  [64*32];
static __device__ float g_postT[64*64];
static __device__ float g_poutT[128*128];

static __device__ float g_lb  [(size_t)4*64*HW];   // local branch residual
static __device__ float g_xpre[(size_t)4*64*HW];   // lgce pre-conv output
static __device__ float g_qkv [(size_t)4*192*HW];  // qkv before dwconv
static __device__ float g_qkvd[(size_t)4*192*HW];  // qkv after dwconv

static __device__ double g_pooled[4*64];
static __device__ double g_gate_sum;
static __device__ double g_resp_sum[4*8];
static __device__ double g_gram[4*8*64];
static __device__ double g_qss[4*64];
static __device__ double g_kss[4*64];
static __device__ float  g_cw[4*64];
static __device__ float  g_kdyn;
static __device__ float  g_attnw[4*8*64];

__device__ __forceinline__ float sigm(float v){ return 1.0f/(1.0f + __expf(-v)); }

// Shared CBAM response path: MUST be identical in k_thr and k_final so that
// resp vs threshold comparisons are bit-consistent across kernels.
__device__ __forceinline__ void group_resp(const float* xv, const float* cw8,
                                           const float* sw8, float sbg, float* resp)
{
  float xc[8]; float dot = sbg;
  #pragma unroll
  for (int c=0;c<8;c++){ xc[c] = xv[c]*cw8[c]; dot = fmaf(xc[c], sw8[c], dot); }
  float sp = sigm(dot);
  #pragma unroll
  for (int c=0;c<8;c++) resp[c] = sigm(xc[c]*sp);
}

// ------------------------------- k_prep -------------------------------
__global__ void k_prep(const float* __restrict__ pw, const float* __restrict__ prew,
                       const float* __restrict__ qw, const float* __restrict__ g1,
                       const float* __restrict__ postw, const float* __restrict__ poutw)
{
  int t = blockIdx.x*256 + threadIdx.x;
  int nt = gridDim.x*256;
  for (int i=t; i<128*128; i+=nt){ int o=i>>7, c=i&127; g_projT[c*128+o]=pw[i]; g_poutT[c*128+o]=poutw[i]; }
  for (int i=t; i<64*64;  i+=nt){ int o=i>>6, c=i&63;  g_preT[c*64+o]=prew[i]; g_postT[c*64+o]=postw[i]; }
  for (int i=t; i<192*64; i+=nt){ int o=i/64, c=i%64;  g_qkvT[c*192+o]=qw[i]; }
  for (int i=t; i<32*64;  i+=nt){ int o=i>>6, c=i&63;  g_g1T[c*32+o]=g1[i]; }
  if (t < 256){ g_pooled[t]=0.0; g_qss[t]=0.0; g_kss[t]=0.0; }
  for (int i=t; i<2048; i+=nt) g_gram[i]=0.0;
  if (t < 32) g_resp_sum[t]=0.0;
  if (t == 0) g_gate_sum=0.0;
}

// ------------------------------- k_front -------------------------------
// smem layout (floats)
#define FR_WS_PROJ 0
#define FR_WS_PRE  (16384)
#define FR_WS_QKV  (20480)
#define FR_WS_G1   (32768)
#define FR_XS      (34816)
#define FR_PS      (43008)
#define FR_HID     (51200)
#define FR_TOTAL   (53312)

__global__ void __launch_bounds__(256) k_front(
    const float* __restrict__ x, const float* __restrict__ pre_b,
    const float* __restrict__ gate_b1, const float* __restrict__ gate_w2,
    const float* __restrict__ gate_b2)
{
  extern __shared__ float sm[];
  float* wsP = sm + FR_WS_PROJ;
  float* wsE = sm + FR_WS_PRE;
  float* wsQ = sm + FR_WS_QKV;
  float* wsG = sm + FR_WS_G1;
  float* xs  = sm + FR_XS;
  float* ps  = sm + FR_PS;
  float* hid = sm + FR_HID;

  int tid = threadIdx.x;
  int b   = blockIdx.x >> 10;
  int pb  = (blockIdx.x & 1023) << 6;
  int tx = tid & 31, ty = tid >> 5;
  int p0 = ty << 3;

  for (int i=tid; i<128*128; i+=256) wsP[i] = g_projT[i];
  for (int i=tid; i<64*64;   i+=256) wsE[i] = g_preT[i];
  for (int i=tid; i<64*192;  i+=256) wsQ[i] = g_qkvT[i];
  for (int i=tid; i<64*32;   i+=256) wsG[i] = g_g1T[i];

  const float* xb = x + (size_t)b*128*HW + pb;
  for (int i=tid; i<128*16; i+=256){
    int ch = i>>4, p4 = i&15;
    float4 v = __ldg((const float4*)(xb + (size_t)ch*HW) + p4);
    *((float4*)(xs + ch*64) + p4) = v;
  }
  __syncthreads();

  // Phase A: input_proj GEMM 128x64, K=128
  {
    float acc[4][8];
    #pragma unroll
    for (int i=0;i<4;i++){
      #pragma unroll
      for (int j=0;j<8;j++) acc[i][j]=0.f;
    }
    #pragma unroll 4
    for (int k=0;k<128;k++){
      float4 w  = *((const float4*)(wsP + k*128) + tx);
      float4 a0 = *((const float4*)(xs + k*64) + (ty<<1));
      float4 a1 = *((const float4*)(xs + k*64) + (ty<<1) + 1);
      float xv[8] = {a0.x,a0.y,a0.z,a0.w,a1.x,a1.y,a1.z,a1.w};
      float wv[4] = {w.x,w.y,w.z,w.w};
      #pragma unroll
      for (int i=0;i<4;i++){
        #pragma unroll
        for (int j=0;j<8;j++) acc[i][j]=fmaf(wv[i],xv[j],acc[i][j]);
      }
    }
    int o0 = tx<<2;
    #pragma unroll
    for (int i=0;i<4;i++){
      #pragma unroll
      for (int j=0;j<8;j++) ps[(o0+i)*64 + p0 + j] = acc[i][j];
    }
  }
  __syncthreads();

  // coalesced lb store (proj rows 0..63)
  {
    float* lbp = g_lb + (size_t)b*64*HW + pb;
    for (int i=tid; i<64*64; i+=256){ int ch=i>>6, p=i&63; lbp[(size_t)ch*HW + p] = ps[i]; }
  }

  // Phase D: gate hidden (32 x 64px, K=64 on gb = ps rows 64..127)
  {
    int o0 = (tid & 3) << 3;
    int p  = tid >> 2;
    float acc[8];
    #pragma unroll
    for (int i=0;i<8;i++) acc[i]=0.f;
    #pragma unroll 4
    for (int k=0;k<64;k++){
      float xv = ps[(64+k)*64 + p];
      float4 w0 = *((const float4*)(wsG + k*32 + o0));
      float4 w1 = *((const float4*)(wsG + k*32 + o0) + 1);
      acc[0]=fmaf(w0.x,xv,acc[0]); acc[1]=fmaf(w0.y,xv,acc[1]);
      acc[2]=fmaf(w0.z,xv,acc[2]); acc[3]=fmaf(w0.w,xv,acc[3]);
      acc[4]=fmaf(w1.x,xv,acc[4]); acc[5]=fmaf(w1.y,xv,acc[5]);
      acc[6]=fmaf(w1.z,xv,acc[6]); acc[7]=fmaf(w1.w,xv,acc[7]);
    }
    #pragma unroll
    for (int i=0;i<8;i++)
      hid[p*33 + o0 + i] = fmaxf(acc[i] + __ldg(gate_b1 + o0 + i), 0.f);
  }
  __syncthreads();

  // Phase E: gate scalar per pixel + global fp64 sum
  if (tid < 64){
    float g = __ldg(gate_b2);
    #pragma unroll
    for (int h=0;h<32;h++) g = fmaf(hid[tid*33+h], __ldg(gate_w2+h), g);
    g = sigm(g);
    #pragma unroll
    for (int off=16; off; off>>=1) g += __shfl_down_sync(0xffffffffu, g, off);
    if ((tid&31)==0) atomicAdd(&g_gate_sum, (double)g);
  }

  // Phase B: lgce pre conv (64 x 64px, K=64 on lb = ps rows 0..63) -> stage xs (stride 65)
  {
    float acc0[8], acc1[8];
    #pragma unroll
    for (int j=0;j<8;j++){ acc0[j]=0.f; acc1[j]=0.f; }
    #pragma unroll 4
    for (int k=0;k<64;k++){
      float2 w  = *((const float2*)(wsE + k*64) + tx);
      float4 a0 = *((const float4*)(ps + k*64) + (ty<<1));
      float4 a1 = *((const float4*)(ps + k*64) + (ty<<1) + 1);
      float xv[8] = {a0.x,a0.y,a0.z,a0.w,a1.x,a1.y,a1.z,a1.w};
      #pragma unroll
      for (int j=0;j<8;j++){ acc0[j]=fmaf(w.x,xv[j],acc0[j]); acc1[j]=fmaf(w.y,xv[j],acc1[j]); }
    }
    int o0 = tx<<1;
    float bb0 = __ldg(pre_b + o0), bb1 = __ldg(pre_b + o0 + 1);
    #pragma unroll
    for (int j=0;j<8;j++){
      xs[o0*65     + p0 + j] = acc0[j] + bb0;
      xs[(o0+1)*65 + p0 + j] = acc1[j] + bb1;
    }
  }
  __syncthreads();

  // xpre store + pooled sums (conflict-free: stride-65 stage)
  {
    float* xp = g_xpre + (size_t)b*64*HW + pb;
    for (int i=tid; i<64*64; i+=256){ int ch=i>>6, p=i&63; xp[(size_t)ch*HW + p] = xs[ch*65 + p]; }
    if (tid < 64){
      float s = 0.f;
      #pragma unroll 8
      for (int p=0;p<64;p++) s += xs[tid*65 + p];
      atomicAdd(&g_pooled[b*64 + tid], (double)s);
    }
  }
  __syncthreads();

  // Phase C: qkv conv (192 x 64px, K=64 on gb)
  {
    int o0 = tx*6;
    float acc[6][8];
    #pragma unroll
    for (int i=0;i<6;i++){
      #pragma unroll
      for (int j=0;j<8;j++) acc[i][j]=0.f;
    }
    #pragma unroll 2
    for (int k=0;k<64;k++){
      const float2* wr = (const float2*)(wsQ + k*192 + o0);
      float2 w0 = wr[0], w1 = wr[1], w2v = wr[2];
      float wv[6] = {w0.x,w0.y,w1.x,w1.y,w2v.x,w2v.y};
      float4 a0 = *((const float4*)(ps + (64+k)*64) + (ty<<1));
      float4 a1 = *((const float4*)(ps + (64+k)*64) + (ty<<1) + 1);
      float xv[8] = {a0.x,a0.y,a0.z,a0.w,a1.x,a1.y,a1.z,a1.w};
      #pragma unroll
      for (int i=0;i<6;i++){
        #pragma unroll
        for (int j=0;j<8;j++) acc[i][j]=fmaf(wv[i],xv[j],acc[i][j]);
      }
    }
    __syncthreads();   // all reads of ps/xs done before overwrite
    #pragma unroll
    for (int i=0;i<6;i++){
      int o = o0 + i;
      float* dst = (o < 128) ? (ps + o*64) : (xs + (o-128)*64);
      #pragma unroll
      for (int j=0;j<8;j++) dst[p0+j] = acc[i][j];
    }
  }
  __syncthreads();
  {
    float* qp = g_qkv + (size_t)b*192*HW + pb;
    for (int i=tid; i<128*64; i+=256){ int ch=i>>6, p=i&63; qp[(size_t)ch*HW + p] = ps[i]; }
    for (int i=tid; i<64*64;  i+=256){ int ch=i>>6, p=i&63; qp[(size_t)(128+ch)*HW + p] = xs[ch*64 + p]; }
  }
}

// ------------------------------- k_dw: depthwise 3x3 SAME -------------------------------
__global__ void __launch_bounds__(256) k_dw(const float* __restrict__ dww)
{
  int bc = blockIdx.x >> 8;     // b*192 + ch, 0..767
  int y  = blockIdx.x & 255;
  int xx = threadIdx.x;
  int ch = bc % 192;
  const float* img = g_qkv + (size_t)bc*HW;
  float w[9];
  #pragma unroll
  for (int i=0;i<9;i++) w[i] = __ldg(dww + ch*9 + i);
  float s = 0.f;
  #pragma unroll
  for (int dy=-1; dy<=1; dy++){
    int yy = y + dy;
    if ((unsigned)yy >= 256u) continue;
    const float* row = img + yy*IMW;
    #pragma unroll
    for (int dx=-1; dx<=1; dx++){
      int xc = xx + dx;
      if ((unsigned)xc >= 256u) continue;
      s = fmaf(__ldg(row + xc), w[(dy+1)*3 + dx + 1], s);
    }
  }
  g_qkvd[(size_t)bc*HW + y*IMW + xx] = s;
}

// ------------------------------- k_small: cw + kdyn -------------------------------
__global__ void k_small(const float* __restrict__ w1, const float* __restrict__ b1,
                        const float* __restrict__ w2, const float* __restrict__ b2)
{
  int t = threadIdx.x;
  if (t < 32){
    int b = t >> 3, g = t & 7;
    float pooled[8];
    #pragma unroll
    for (int c=0;c<8;c++) pooled[c] = (float)(g_pooled[b*64 + g*8 + c] * (1.0/65536.0));
    float h0 = b1[g*2+0], h1 = b1[g*2+1];
    #pragma unroll
    for (int c=0;c<8;c++){
      h0 = fmaf(pooled[c], w1[g*16 + 0*8 + c], h0);
      h1 = fmaf(pooled[c], w1[g*16 + 1*8 + c], h1);
    }
    h0 = fmaxf(h0, 0.f); h1 = fmaxf(h1, 0.f);
    #pragma unroll
    for (int c=0;c<8;c++){
      float v = b2[g*8+c];
      v = fmaf(h0, w2[g*16 + c*2 + 0], v);
      v = fmaf(h1, w2[g*16 + c*2 + 1], v);
      g_cw[b*64 + g*8 + c] = sigm(v);
    }
    if (t == 0){
      float mean = (float)(g_gate_sum * (1.0/262144.0));
      g_kdyn = fminf(fmaxf(floorf(8.f*mean), 1.f), 8.f);
    }
  }
}

// ------------------------------- k_thr: resp threshold sums -------------------------------
__global__ void __launch_bounds__(256) k_thr(const float* __restrict__ sw, const float* __restrict__ sb)
{
  __shared__ float cw_s[64], sw_s[64], sb_s[8];
  __shared__ float ssum[8];
  int tid = threadIdx.x;
  int b = blockIdx.x >> 8;
  int p = ((blockIdx.x & 255) << 8) + tid;
  if (tid < 64){ cw_s[tid] = g_cw[b*64 + tid]; sw_s[tid] = __ldg(sw + tid); }
  if (tid < 8){ sb_s[tid] = __ldg(sb + tid); ssum[tid] = 0.f; }
  __syncthreads();
  const float* xp = g_xpre + (size_t)b*64*HW + p;
  float rs[8];
  #pragma unroll
  for (int g=0; g<8; g++){
    float xv[8], resp[8];
    #pragma unroll
    for (int c=0;c<8;c++) xv[c] = __ldg(xp + (size_t)(g*8+c)*HW);
    group_resp(xv, cw_s + g*8, sw_s + g*8, sb_s[g], resp);
    float s = 0.f;
    #pragma unroll
    for (int c=0;c<8;c++) s += resp[c];
    rs[g] = s;
  }
  #pragma unroll
  for (int g=0;g<8;g++) atomicAdd(&ssum[g], rs[g]);
  __syncthreads();
  if (tid < 8) atomicAdd(&g_resp_sum[b*8 + tid], (double)ssum[tid]);
}

// ------------------------------- k_gram -------------------------------
__global__ void __launch_bounds__(256) k_gram()
{
  __shared__ double red[80];
  int tid = threadIdx.x;
  int b  = blockIdx.x >> 6;
  int h  = (blockIdx.x >> 3) & 7;
  int sl = blockIdx.x & 7;
  const float* qb = g_qkvd + (size_t)(b*192 + h*8)*HW;
  const float* kb = g_qkvd + (size_t)(b*192 + 64 + h*8)*HW;

  float gr[8][8], qs[8], ks[8];
  #pragma unroll
  for (int c=0;c<8;c++){
    qs[c]=0.f; ks[c]=0.f;
    #pragma unroll
    for (int d=0;d<8;d++) gr[c][d]=0.f;
  }
  int p0 = sl*8192 + tid;
  for (int it=0; it<32; it++){
    int p = p0 + it*256;
    float q[8], k[8];
    #pragma unroll
    for (int c=0;c<8;c++){ q[c]=__ldg(qb + (size_t)c*HW + p); k[c]=__ldg(kb + (size_t)c*HW + p); }
    #pragma unroll
    for (int c=0;c<8;c++){
      qs[c]=fmaf(q[c],q[c],qs[c]); ks[c]=fmaf(k[c],k[c],ks[c]);
      #pragma unroll
      for (int d=0;d<8;d++) gr[c][d]=fmaf(q[c],k[d],gr[c][d]);
    }
  }
  if (tid < 80) red[tid] = 0.0;
  __syncthreads();
  #pragma unroll
  for (int c=0;c<8;c++){
    #pragma unroll
    for (int d=0;d<8;d++) atomicAdd(&red[c*8+d], (double)gr[c][d]);
    atomicAdd(&red[64+c], (double)qs[c]);
    atomicAdd(&red[72+c], (double)ks[c]);
  }
  __syncthreads();
  if (tid < 64) atomicAdd(&g_gram[(b*8+h)*64 + tid], red[tid]);
  else if (tid < 72) atomicAdd(&g_qss[b*64 + h*8 + (tid-64)], red[tid]);
  else if (tid < 80) atomicAdd(&g_kss[b*64 + h*8 + (tid-72)], red[tid]);
}

// ------------------------------- k_attn -------------------------------
__global__ void k_attn(const float* __restrict__ temp, const float* __restrict__ scales)
{
  int t = threadIdx.x;
  if (t >= 32) return;
  int b = t >> 3, h = t & 7;
  float scl = scales[0] + scales[1] + scales[2] + scales[3];
  float T   = temp[h];
  float kd  = g_kdyn;
  float nq[8], nk[8];
  #pragma unroll
  for (int c=0;c<8;c++){
    nq[c] = fmaxf(sqrtf((float)g_qss[b*64 + h*8 + c]), 1e-12f);
    nk[c] = fmaxf(sqrtf((float)g_kss[b*64 + h*8 + c]), 1e-12f);
  }
  float a[8][8];
  #pragma unroll
  for (int c=0;c<8;c++){
    #pragma unroll
    for (int d=0;d<8;d++)
      a[c][d] = ((float)g_gram[(b*8+h)*64 + c*8 + d]) / (nq[c]*nk[d]) * T;
  }
  #pragma unroll
  for (int c=0;c<8;c++){
    bool keep[8];
    #pragma unroll
    for (int d=0;d<8;d++){
      int r = 0;
      #pragma unroll
      for (int e=0;e<8;e++)
        r += (a[c][e] > a[c][d]) || (a[c][e] == a[c][d] && e < d);
      keep[d] = ((float)r < kd);
    }
    float m = -1e30f;
    #pragma unroll
    for (int d=0;d<8;d++) if (keep[d]) m = fmaxf(m, a[c][d]);
    float pr[8]; float sum = 0.f;
    #pragma unroll
    for (int d=0;d<8;d++){ pr[d] = keep[d] ? __expf(a[c][d]-m) : 0.f; sum += pr[d]; }
    float inv = scl / sum;
    #pragma unroll
    for (int d=0;d<8;d++) g_attnw[((b*8+h)*8 + c)*8 + d] = pr[d]*inv;
  }
}

// ------------------------------- k_final -------------------------------
#define FN_WPOUT 0
#define FN_WPOST (16384)
#define FN_FUSED (20480)
#define FN_XS    (28672)
#define FN_VB    (32768)
#define FN_W     (36864)
#define FN_CW    (37376)
#define FN_THR   (37440)
#define FN_TOTAL (37448)

__global__ void __launch_bounds__(256) k_final(
    const float* __restrict__ sw, const float* __restrict__ sb,
    const float* __restrict__ post_b, float* __restrict__ out)
{
  extern __shared__ float sm[];
  float* wpout = sm + FN_WPOUT;
  float* wpost = sm + FN_WPOST;
  float* fused = sm + FN_FUSED;
  float* xs    = sm + FN_XS;
  float* vb    = sm + FN_VB;
  float* W_s   = sm + FN_W;
  float* cw_s  = sm + FN_CW;
  float* thr_s = sm + FN_THR;

  int tid = threadIdx.x;
  int b   = blockIdx.x >> 10;
  int pb  = (blockIdx.x & 1023) << 6;
  int tx = tid & 31, ty = tid >> 5;
  int p0 = ty << 3;

  for (int i=tid; i<16384; i+=256) wpout[i] = g_poutT[i];
  for (int i=tid; i<4096;  i+=256) wpost[i] = g_postT[i];
  for (int i=tid; i<512;   i+=256) W_s[i]   = g_attnw[b*512 + i];
  if (tid < 64) cw_s[tid] = g_cw[b*64 + tid];
  if (tid < 8)  thr_s[tid] = (float)(g_resp_sum[b*8 + tid] * (1.0/524288.0));
  {
    const float* xp  = g_xpre + (size_t)b*64*HW + pb;
    const float* lbp = g_lb   + (size_t)b*64*HW + pb;
    for (int i=tid; i<64*64; i+=256){
      int ch=i>>6, p=i&63;
      xs[i] = xp[(size_t)ch*HW + p];
      vb[i] = lbp[(size_t)ch*HW + p];
    }
  }
  __syncthreads();

  // mask in place (same group_resp as k_thr)
  {
    int p  = tid & 63;
    int g0 = (tid >> 6) << 1;
    #pragma unroll
    for (int gi=0; gi<2; gi++){
      int g = g0 + gi;
      float xv[8], resp[8], sw8[8];
      #pragma unroll
      for (int c=0;c<8;c++){ xv[c] = xs[(g*8+c)*64 + p]; sw8[c] = __ldg(sw + g*8 + c); }
      group_resp(xv, cw_s + g*8, sw8, __ldg(sb + g), resp);
      float thr = thr_s[g];
      #pragma unroll
      for (int c=0;c<8;c++){
        float m = resp[c] > thr ? 1.f : resp[c];
        xs[(g*8+c)*64 + p] = xv[c]*m;
      }
    }
  }
  __syncthreads();

  // post conv + bias + residual -> fused rows 64..127
  {
    float acc0[8], acc1[8];
    #pragma unroll
    for (int j=0;j<8;j++){ acc0[j]=0.f; acc1[j]=0.f; }
    #pragma unroll 4
    for (int k=0;k<64;k++){
      float2 w  = *((const float2*)(wpost + k*64) + tx);
      float4 a0 = *((const float4*)(xs + k*64) + (ty<<1));
      float4 a1 = *((const float4*)(xs + k*64) + (ty<<1) + 1);
      float xv[8] = {a0.x,a0.y,a0.z,a0.w,a1.x,a1.y,a1.z,a1.w};
      #pragma unroll
      for (int j=0;j<8;j++){ acc0[j]=fmaf(w.x,xv[j],acc0[j]); acc1[j]=fmaf(w.y,xv[j],acc1[j]); }
    }
    int o0 = tx<<1;
    float bb0 = __ldg(post_b + o0), bb1 = __ldg(post_b + o0 + 1);
    #pragma unroll
    for (int j=0;j<8;j++){
      fused[(64+o0)*64   + p0 + j] = acc0[j] + bb0 + vb[o0*64 + p0 + j];
      fused[(64+o0+1)*64 + p0 + j] = acc1[j] + bb1 + vb[(o0+1)*64 + p0 + j];
    }
  }
  __syncthreads();

  // load v tile (dwconv'd), attn mix -> fused rows 0..63
  {
    const float* vp = g_qkvd + (size_t)(b*192 + 128)*HW + pb;
    for (int i=tid; i<64*64; i+=256){ int ch=i>>6, p=i&63; vb[i] = vp[(size_t)ch*HW + p]; }
  }
  __syncthreads();
  {
    int o0 = tx<<1;
    #pragma unroll
    for (int i=0;i<2;i++){
      int o = o0 + i, h = o>>3, ci = o&7;
      float acc[8];
      #pragma unroll
      for (int j=0;j<8;j++) acc[j]=0.f;
      #pragma unroll
      for (int d=0;d<8;d++){
        float w = W_s[(h*8+ci)*8 + d];
        #pragma unroll
        for (int j=0;j<8;j++) acc[j]=fmaf(w, vb[(h*8+d)*64 + p0 + j], acc[j]);
      }
      #pragma unroll
      for (int j=0;j<8;j++) fused[o*64 + p0 + j] = acc[j];
    }
  }
  __syncthreads();

  // proj_out GEMM 128x64, K=128
  {
    float acc[4][8];
    #pragma unroll
    for (int i=0;i<4;i++){
      #pragma unroll
      for (int j=0;j<8;j++) acc[i][j]=0.f;
    }
    #pragma unroll 4
    for (int k=0;k<128;k++){
      float4 w  = *((const float4*)(wpout + k*128) + tx);
      float4 a0 = *((const float4*)(fused + k*64) + (ty<<1));
      float4 a1 = *((const float4*)(fused + k*64) + (ty<<1) + 1);
      float xv[8] = {a0.x,a0.y,a0.z,a0.w,a1.x,a1.y,a1.z,a1.w};
      float wv[4] = {w.x,w.y,w.z,w.w};
      #pragma unroll
      for (int i=0;i<4;i++){
        #pragma unroll
        for (int j=0;j<8;j++) acc[i][j]=fmaf(wv[i],xv[j],acc[i][j]);
      }
    }
    __syncthreads();   // all reads of fused complete
    int o0 = tx<<2;
    #pragma unroll
    for (int i=0;i<4;i++){
      #pragma unroll
      for (int j=0;j<8;j++) fused[(o0+i)*64 + p0 + j] = acc[i][j];
    }
  }
  __syncthreads();
  {
    float* op = out + (size_t)b*128*HW + pb;
    for (int i=tid; i<128*64; i+=256){ int ch=i>>6, p=i&63; op[(size_t)ch*HW + p] = fused[i]; }
  }
}

// ------------------------------- launch -------------------------------
extern "C" void kernel_launch(void* const* d_in, const int* in_sizes, int n_in,
                              void* d_out, int out_size)
{
  const float* x      = (const float*)d_in[0];
  const float* projw  = (const float*)d_in[1];
  const float* prew   = (const float*)d_in[2];
  const float* preb   = (const float*)d_in[3];
  const float* w1     = (const float*)d_in[4];
  const float* b1     = (const float*)d_in[5];
  const float* w2     = (const float*)d_in[6];
  const float* b2     = (const float*)d_in[7];
  const float* sw     = (const float*)d_in[8];
  const float* sb     = (const float*)d_in[9];
  const float* postw  = (const float*)d_in[10];
  const float* postb  = (const float*)d_in[11];
  const float* qkvw   = (const float*)d_in[12];
  const float* dww    = (const float*)d_in[13];
  const float* gw1    = (const float*)d_in[14];
  const float* gb1    = (const float*)d_in[15];
  const float* gw2    = (const float*)d_in[16];
  const float* gb2    = (const float*)d_in[17];
  const float* temp   = (const float*)d_in[18];
  const float* scales = (const float*)d_in[19];
  const float* poutw  = (const float*)d_in[20];
  float* out = (float*)d_out;

  cudaFuncSetAttribute(k_front, cudaFuncAttributeMaxDynamicSharedMemorySize, FR_TOTAL*4);
  cudaFuncSetAttribute(k_final, cudaFuncAttributeMaxDynamicSharedMemorySize, FN_TOTAL*4);

  k_prep <<<64, 256>>>(projw, prew, qkvw, gw1, postw, poutw);
  k_front<<<4096, 256, FR_TOTAL*4>>>(x, preb, gb1, gw2, gb2);
  k_dw   <<<768*256, 256>>>(dww);
  k_small<<<1, 32>>>(w1, b1, w2, b2);
  k_thr  <<<1024, 256>>>(sw, sb);
  k_gram <<<256, 256>>>();
  k_attn <<<1, 32>>>(temp, scales);
  k_final<<<4096, 256, FN_TOTAL*4>>>(sw, sb, postb, out);
}

// round 4
// speedup vs baseline: 1.3445x; 1.3445x over previous
#include <cuda_runtime.h>

#define HW 65536
#define IMW 256

// ------------------------- device scratch (no allocations) -------------------------
static __device__ __align__(16) float g_projT[128*128];
static __device__ __align__(16) float g_preT [64*64];
static __device__ __align__(16) float g_qkvT [64*192];
static __device__ __align__(16) float g_g1T  [64*32];
static __device__ __align__(16) float g_postT[64*64];
static __device__ __align__(16) float g_poutT[128*128];

static __device__ __align__(16) float g_lb  [(size_t)4*64*HW];   // local branch residual
static __device__ __align__(16) float g_xpre[(size_t)4*64*HW];   // lgce pre-conv output
static __device__ __align__(16) float g_qkv [(size_t)4*192*HW];  // qkv before dwconv
static __device__ __align__(16) float g_qkvd[(size_t)4*192*HW];  // qkv after dwconv

static __device__ double g_pooled[4*64];
static __device__ double g_gate_sum;
static __device__ double g_resp_sum[4*8];
static __device__ double g_gram[4*8*64];
static __device__ double g_qss[4*64];
static __device__ double g_kss[4*64];
static __device__ float  g_cw[4*64];
static __device__ float  g_kdyn;
static __device__ float  g_attnw[4*8*64];

__device__ __forceinline__ float sigm(float v){ return 1.0f/(1.0f + __expf(-v)); }

// ---- packed f32x2 helpers (SASS FFMA2; ptxas never emits it from C++) ----
typedef unsigned long long u64;
__device__ __forceinline__ u64 pk2(float lo, float hi){
  u64 r; asm("mov.b64 %0, {%1,%2};" : "=l"(r) : "f"(lo), "f"(hi)); return r;
}
__device__ __forceinline__ void fma2(u64 &d, u64 a, u64 b){
  asm("fma.rn.f32x2 %0, %1, %2, %0;" : "+l"(d) : "l"(a), "l"(b));
}
__device__ __forceinline__ float2 upk2(u64 v){
  float2 f; asm("mov.b64 {%0,%1}, %2;" : "=f"(f.x), "=f"(f.y) : "l"(v)); return f;
}

// Shared CBAM response path: MUST be identical in k_thr and k_final so that
// resp vs threshold comparisons are bit-consistent across kernels.
__device__ __forceinline__ void group_resp(const float* xv, const float* cw8,
                                           const float* sw8, float sbg, float* resp)
{
  float xc[8]; float dot = sbg;
  #pragma unroll
  for (int c=0;c<8;c++){ xc[c] = xv[c]*cw8[c]; dot = fmaf(xc[c], sw8[c], dot); }
  float sp = sigm(dot);
  #pragma unroll
  for (int c=0;c<8;c++) resp[c] = sigm(xc[c]*sp);
}

// ------------------------------- k_prep -------------------------------
__global__ void k_prep(const float* __restrict__ pw, const float* __restrict__ prew,
                       const float* __restrict__ qw, const float* __restrict__ g1,
                       const float* __restrict__ postw, const float* __restrict__ poutw)
{
  int t = blockIdx.x*256 + threadIdx.x;
  int nt = gridDim.x*256;
  for (int i=t; i<128*128; i+=nt){ int o=i>>7, c=i&127; g_projT[c*128+o]=pw[i]; g_poutT[c*128+o]=poutw[i]; }
  for (int i=t; i<64*64;  i+=nt){ int o=i>>6, c=i&63;  g_preT[c*64+o]=prew[i]; g_postT[c*64+o]=postw[i]; }
  for (int i=t; i<192*64; i+=nt){ int o=i/64, c=i%64;  g_qkvT[c*192+o]=qw[i]; }
  for (int i=t; i<32*64;  i+=nt){ int o=i>>6, c=i&63;  g_g1T[c*32+o]=g1[i]; }
  if (t < 256){ g_pooled[t]=0.0; g_qss[t]=0.0; g_kss[t]=0.0; }
  for (int i=t; i<2048; i+=nt) g_gram[i]=0.0;
  if (t < 32) g_resp_sum[t]=0.0;
  if (t == 0) g_gate_sum=0.0;
}

// ------------------------------- k_front -------------------------------
// smem layout (floats)
#define FR_WS_PROJ 0
#define FR_WS_PRE  (16384)
#define FR_WS_QKV  (20480)
#define FR_WS_G1   (32768)
#define FR_XS      (34816)
#define FR_PS      (43008)
#define FR_HID     (51200)
#define FR_TOTAL   (53312)

__global__ void __launch_bounds__(256) k_front(
    const float* __restrict__ x, const float* __restrict__ pre_b,
    const float* __restrict__ gate_b1, const float* __restrict__ gate_w2,
    const float* __restrict__ gate_b2)
{
  extern __shared__ float sm[];
  float* wsP = sm + FR_WS_PROJ;
  float* wsE = sm + FR_WS_PRE;
  float* wsQ = sm + FR_WS_QKV;
  float* wsG = sm + FR_WS_G1;
  float* xs  = sm + FR_XS;
  float* ps  = sm + FR_PS;
  float* hid = sm + FR_HID;

  int tid = threadIdx.x;
  int b   = blockIdx.x >> 10;
  int pb  = (blockIdx.x & 1023) << 6;
  int tx = tid & 31, ty = tid >> 5;
  int p0 = ty << 3;

  // vectorized weight fills (g_* are L2-resident after wave 1)
  for (int i=tid; i<128*32; i+=256) ((float4*)wsP)[i] = ((const float4*)g_projT)[i];
  for (int i=tid; i<64*16;  i+=256) ((float4*)wsE)[i] = ((const float4*)g_preT)[i];
  for (int i=tid; i<64*48;  i+=256) ((float4*)wsQ)[i] = ((const float4*)g_qkvT)[i];
  for (int i=tid; i<64*8;   i+=256) ((float4*)wsG)[i] = ((const float4*)g_g1T)[i];

  const float* xb = x + (size_t)b*128*HW + pb;
  for (int i=tid; i<128*16; i+=256){
    int ch = i>>4, p4 = i&15;
    float4 v = __ldg((const float4*)(xb + (size_t)ch*HW) + p4);
    *((float4*)(xs + ch*64) + p4) = v;
  }
  __syncthreads();

  // Phase A: input_proj GEMM 128x64, K=128 (f32x2: 4 outs x 4 px-pairs)
  {
    u64 acc[4][4];
    #pragma unroll
    for (int i=0;i<4;i++){
      #pragma unroll
      for (int j=0;j<4;j++) acc[i][j]=0ull;
    }
    #pragma unroll 4
    for (int k=0;k<128;k++){
      float4 w  = *((const float4*)(wsP + k*128) + tx);
      float4 a0 = *((const float4*)(xs + k*64) + (ty<<1));
      float4 a1 = *((const float4*)(xs + k*64) + (ty<<1) + 1);
      u64 xp[4] = {pk2(a0.x,a0.y), pk2(a0.z,a0.w), pk2(a1.x,a1.y), pk2(a1.z,a1.w)};
      u64 wp;
      wp = pk2(w.x,w.x);
      fma2(acc[0][0],wp,xp[0]); fma2(acc[0][1],wp,xp[1]); fma2(acc[0][2],wp,xp[2]); fma2(acc[0][3],wp,xp[3]);
      wp = pk2(w.y,w.y);
      fma2(acc[1][0],wp,xp[0]); fma2(acc[1][1],wp,xp[1]); fma2(acc[1][2],wp,xp[2]); fma2(acc[1][3],wp,xp[3]);
      wp = pk2(w.z,w.z);
      fma2(acc[2][0],wp,xp[0]); fma2(acc[2][1],wp,xp[1]); fma2(acc[2][2],wp,xp[2]); fma2(acc[2][3],wp,xp[3]);
      wp = pk2(w.w,w.w);
      fma2(acc[3][0],wp,xp[0]); fma2(acc[3][1],wp,xp[1]); fma2(acc[3][2],wp,xp[2]); fma2(acc[3][3],wp,xp[3]);
    }
    int o0 = tx<<2;
    #pragma unroll
    for (int i=0;i<4;i++){
      #pragma unroll
      for (int j=0;j<4;j++){
        float2 v = upk2(acc[i][j]);
        *((float2*)(ps + (o0+i)*64 + p0 + 2*j)) = v;
      }
    }
  }
  __syncthreads();

  // coalesced lb store (proj rows 0..63), float4
  {
    float* lbp = g_lb + (size_t)b*64*HW + pb;
    for (int i=tid; i<64*16; i+=256){
      int ch=i>>4, q=i&15;
      *((float4*)(lbp + (size_t)ch*HW) + q) = *((const float4*)(ps + ch*64) + q);
    }
  }

  // Phase D: gate hidden (32 x 64px, K=64 on gb = ps rows 64..127) -- f32x2 over outputs
  {
    int o0 = (tid & 3) << 3;
    int p  = tid >> 2;
    u64 acc[4];
    #pragma unroll
    for (int i=0;i<4;i++) acc[i]=0ull;
    #pragma unroll 4
    for (int k=0;k<64;k++){
      float xv = ps[(64+k)*64 + p];
      u64 xp = pk2(xv,xv);
      float4 w0 = *((const float4*)(wsG + k*32 + o0));
      float4 w1 = *((const float4*)(wsG + k*32 + o0) + 1);
      fma2(acc[0], pk2(w0.x,w0.y), xp);
      fma2(acc[1], pk2(w0.z,w0.w), xp);
      fma2(acc[2], pk2(w1.x,w1.y), xp);
      fma2(acc[3], pk2(w1.z,w1.w), xp);
    }
    #pragma unroll
    for (int i=0;i<4;i++){
      float2 v = upk2(acc[i]);
      hid[p*33 + o0 + 2*i]     = fmaxf(v.x + __ldg(gate_b1 + o0 + 2*i), 0.f);
      hid[p*33 + o0 + 2*i + 1] = fmaxf(v.y + __ldg(gate_b1 + o0 + 2*i + 1), 0.f);
    }
  }
  __syncthreads();

  // Phase E: gate scalar per pixel + global fp64 sum
  if (tid < 64){
    float g = __ldg(gate_b2);
    #pragma unroll
    for (int h=0;h<32;h++) g = fmaf(hid[tid*33+h], __ldg(gate_w2+h), g);
    g = sigm(g);
    #pragma unroll
    for (int off=16; off; off>>=1) g += __shfl_down_sync(0xffffffffu, g, off);
    if ((tid&31)==0) atomicAdd(&g_gate_sum, (double)g);
  }

  // Phase B: lgce pre conv (64 x 64px, K=64 on lb) -> stage xs (stride 65), f32x2
  {
    u64 acc[2][4];
    #pragma unroll
    for (int i=0;i<2;i++){
      #pragma unroll
      for (int j=0;j<4;j++) acc[i][j]=0ull;
    }
    #pragma unroll 4
    for (int k=0;k<64;k++){
      float2 w  = *((const float2*)(wsE + k*64) + tx);
      float4 a0 = *((const float4*)(ps + k*64) + (ty<<1));
      float4 a1 = *((const float4*)(ps + k*64) + (ty<<1) + 1);
      u64 xp[4] = {pk2(a0.x,a0.y), pk2(a0.z,a0.w), pk2(a1.x,a1.y), pk2(a1.z,a1.w)};
      u64 wp0 = pk2(w.x,w.x), wp1 = pk2(w.y,w.y);
      #pragma unroll
      for (int j=0;j<4;j++){ fma2(acc[0][j],wp0,xp[j]); fma2(acc[1][j],wp1,xp[j]); }
    }
    int o0 = tx<<1;
    float bb0 = __ldg(pre_b + o0), bb1 = __ldg(pre_b + o0 + 1);
    #pragma unroll
    for (int j=0;j<4;j++){
      float2 v0 = upk2(acc[0][j]);
      float2 v1 = upk2(acc[1][j]);
      xs[o0*65     + p0 + 2*j]   = v0.x + bb0;
      xs[o0*65     + p0 + 2*j+1] = v0.y + bb0;
      xs[(o0+1)*65 + p0 + 2*j]   = v1.x + bb1;
      xs[(o0+1)*65 + p0 + 2*j+1] = v1.y + bb1;
    }
  }
  __syncthreads();

  // xpre store (assemble float4 from stride-65 stage) + pooled sums
  {
    float* xp = g_xpre + (size_t)b*64*HW + pb;
    for (int i=tid; i<64*16; i+=256){
      int ch=i>>4, q=i&15;
      float4 v;
      v.x = xs[ch*65 + q*4];   v.y = xs[ch*65 + q*4+1];
      v.z = xs[ch*65 + q*4+2]; v.w = xs[ch*65 + q*4+3];
      *((float4*)(xp + (size_t)ch*HW) + q) = v;
    }
    if (tid < 64){
      float s = 0.f;
      #pragma unroll 8
      for (int p=0;p<64;p++) s += xs[tid*65 + p];
      atomicAdd(&g_pooled[b*64 + tid], (double)s);
    }
  }
  __syncthreads();

  // Phase C: qkv conv (192 x 64px, K=64 on gb), f32x2
  {
    int o0 = tx*6;
    u64 acc[6][4];
    #pragma unroll
    for (int i=0;i<6;i++){
      #pragma unroll
      for (int j=0;j<4;j++) acc[i][j]=0ull;
    }
    #pragma unroll 2
    for (int k=0;k<64;k++){
      const float2* wr = (const float2*)(wsQ + k*192 + o0);
      float2 w0 = wr[0], w1 = wr[1], w2v = wr[2];
      float4 a0 = *((const float4*)(ps + (64+k)*64) + (ty<<1));
      float4 a1 = *((const float4*)(ps + (64+k)*64) + (ty<<1) + 1);
      u64 xp[4] = {pk2(a0.x,a0.y), pk2(a0.z,a0.w), pk2(a1.x,a1.y), pk2(a1.z,a1.w)};
      u64 wp[6] = {pk2(w0.x,w0.x), pk2(w0.y,w0.y), pk2(w1.x,w1.x),
                   pk2(w1.y,w1.y), pk2(w2v.x,w2v.x), pk2(w2v.y,w2v.y)};
      #pragma unroll
      for (int i=0;i<6;i++){
        #pragma unroll
        for (int j=0;j<4;j++) fma2(acc[i][j],wp[i],xp[j]);
      }
    }
    __syncthreads();   // all reads of ps/xs done before overwrite
    #pragma unroll
    for (int i=0;i<6;i++){
      int o = o0 + i;
      float* dst = (o < 128) ? (ps + o*64) : (xs + (o-128)*64);
      #pragma unroll
      for (int j=0;j<4;j++){
        float2 v = upk2(acc[i][j]);
        *((float2*)(dst + p0 + 2*j)) = v;
      }
    }
  }
  __syncthreads();
  {
    float* qp = g_qkv + (size_t)b*192*HW + pb;
    for (int i=tid; i<128*16; i+=256){
      int ch=i>>4, q=i&15;
      *((float4*)(qp + (size_t)ch*HW) + q) = *((const float4*)(ps + ch*64) + q);
    }
    for (int i=tid; i<64*16; i+=256){
      int ch=i>>4, q=i&15;
      *((float4*)(qp + (size_t)(128+ch)*HW) + q) = *((const float4*)(xs + ch*64) + q);
    }
  }
}

// ------------------------------- k_dw: depthwise 3x3 SAME, 4px/thread -------------------------------
__global__ void __launch_bounds__(256) k_dw(const float* __restrict__ dww)
{
  int bid = blockIdx.x;                 // 768 * 64
  int bc  = bid >> 6;                   // b*192 + ch
  int y   = ((bid & 63) << 2) + (threadIdx.x >> 6);
  int xq  = (threadIdx.x & 63) << 2;
  int ch  = bc % 192;
  float w[9];
  #pragma unroll
  for (int i=0;i<9;i++) w[i] = __ldg(dww + ch*9 + i);
  const float* img = g_qkv + (size_t)bc*HW;
  float v[3][6];
  #pragma unroll
  for (int r=0;r<3;r++){
    int yy = y - 1 + r;
    if ((unsigned)yy < 256u){
      float4 c4 = __ldg((const float4*)(img + yy*IMW + xq));
      v[r][1]=c4.x; v[r][2]=c4.y; v[r][3]=c4.z; v[r][4]=c4.w;
      v[r][0] = (xq > 0)   ? __ldg(img + yy*IMW + xq - 1) : 0.f;
      v[r][5] = (xq < 252) ? __ldg(img + yy*IMW + xq + 4) : 0.f;
    } else {
      #pragma unroll
      for (int j=0;j<6;j++) v[r][j]=0.f;
    }
  }
  float o[4];
  #pragma unroll
  for (int j=0;j<4;j++){
    float s=0.f;
    #pragma unroll
    for (int r=0;r<3;r++){
      s = fmaf(v[r][j],   w[r*3+0], s);
      s = fmaf(v[r][j+1], w[r*3+1], s);
      s = fmaf(v[r][j+2], w[r*3+2], s);
    }
    o[j]=s;
  }
  float4 ov = {o[0],o[1],o[2],o[3]};
  *((float4*)(g_qkvd + (size_t)bc*HW + y*IMW + xq)) = ov;
}

// ------------------------------- k_small: cw + kdyn -------------------------------
__global__ void k_small(const float* __restrict__ w1, const float* __restrict__ b1,
                        const float* __restrict__ w2, const float* __restrict__ b2)
{
  int t = threadIdx.x;
  if (t < 32){
    int b = t >> 3, g = t & 7;
    float pooled[8];
    #pragma unroll
    for (int c=0;c<8;c++) pooled[c] = (float)(g_pooled[b*64 + g*8 + c] * (1.0/65536.0));
    float h0 = b1[g*2+0], h1 = b1[g*2+1];
    #pragma unroll
    for (int c=0;c<8;c++){
      h0 = fmaf(pooled[c], w1[g*16 + 0*8 + c], h0);
      h1 = fmaf(pooled[c], w1[g*16 + 1*8 + c], h1);
    }
    h0 = fmaxf(h0, 0.f); h1 = fmaxf(h1, 0.f);
    #pragma unroll
    for (int c=0;c<8;c++){
      float v = b2[g*8+c];
      v = fmaf(h0, w2[g*16 + c*2 + 0], v);
      v = fmaf(h1, w2[g*16 + c*2 + 1], v);
      g_cw[b*64 + g*8 + c] = sigm(v);
    }
    if (t == 0){
      float mean = (float)(g_gate_sum * (1.0/262144.0));
      g_kdyn = fminf(fmaxf(floorf(8.f*mean), 1.f), 8.f);
    }
  }
}

// ------------------------------- k_thr: resp threshold sums (4px/thread) -------------------------------
__global__ void __launch_bounds__(256) k_thr(const float* __restrict__ sw, const float* __restrict__ sb)
{
  __shared__ float cw_s[64], sw_s[64], sb_s[8];
  __shared__ float ssum[8];
  int tid = threadIdx.x;
  int b = blockIdx.x >> 6;
  int p = ((blockIdx.x & 63) << 10) + tid*4;
  if (tid < 64){ cw_s[tid] = g_cw[b*64 + tid]; sw_s[tid] = __ldg(sw + tid); }
  if (tid < 8){ sb_s[tid] = __ldg(sb + tid); ssum[tid] = 0.f; }
  __syncthreads();
  const float* xp = g_xpre + (size_t)b*64*HW + p;
  #pragma unroll
  for (int g=0; g<8; g++){
    float4 xv4[8];
    #pragma unroll
    for (int c=0;c<8;c++) xv4[c] = __ldg((const float4*)(xp + (size_t)(g*8+c)*HW));
    float s = 0.f;
    #pragma unroll
    for (int px=0; px<4; px++){
      float xv[8], resp[8];
      #pragma unroll
      for (int c=0;c<8;c++) xv[c] = ((const float*)&xv4[c])[px];
      group_resp(xv, cw_s + g*8, sw_s + g*8, sb_s[g], resp);
      #pragma unroll
      for (int c=0;c<8;c++) s += resp[c];
    }
    #pragma unroll
    for (int off=16; off; off>>=1) s += __shfl_down_sync(0xffffffffu, s, off);
    if ((tid&31)==0) atomicAdd(&ssum[g], s);
  }
  __syncthreads();
  if (tid < 8) atomicAdd(&g_resp_sum[b*8 + tid], (double)ssum[tid]);
}

// ------------------------------- k_gram (float2 loads) -------------------------------
__global__ void __launch_bounds__(256) k_gram()
{
  __shared__ double red[80];
  int tid = threadIdx.x;
  int b  = blockIdx.x >> 6;
  int h  = (blockIdx.x >> 3) & 7;
  int sl = blockIdx.x & 7;
  const float* qb = g_qkvd + (size_t)(b*192 + h*8)*HW;
  const float* kb = g_qkvd + (size_t)(b*192 + 64 + h*8)*HW;

  float gr[8][8], qs[8], ks[8];
  #pragma unroll
  for (int c=0;c<8;c++){
    qs[c]=0.f; ks[c]=0.f;
    #pragma unroll
    for (int d=0;d<8;d++) gr[c][d]=0.f;
  }
  for (int it=0; it<16; it++){
    int p = sl*8192 + it*512 + tid*2;
    float2 q[8], k[8];
    #pragma unroll
    for (int c=0;c<8;c++){
      q[c]=__ldg((const float2*)(qb + (size_t)c*HW + p));
      k[c]=__ldg((const float2*)(kb + (size_t)c*HW + p));
    }
    #pragma unroll
    for (int c=0;c<8;c++){
      qs[c]=fmaf(q[c].x,q[c].x,qs[c]); qs[c]=fmaf(q[c].y,q[c].y,qs[c]);
      ks[c]=fmaf(k[c].x,k[c].x,ks[c]); ks[c]=fmaf(k[c].y,k[c].y,ks[c]);
      #pragma unroll
      for (int d=0;d<8;d++){
        gr[c][d]=fmaf(q[c].x,k[d].x,gr[c][d]);
        gr[c][d]=fmaf(q[c].y,k[d].y,gr[c][d]);
      }
    }
  }
  if (tid < 80) red[tid] = 0.0;
  __syncthreads();
  #pragma unroll
  for (int c=0;c<8;c++){
    #pragma unroll
    for (int d=0;d<8;d++) atomicAdd(&red[c*8+d], (double)gr[c][d]);
    atomicAdd(&red[64+c], (double)qs[c]);
    atomicAdd(&red[72+c], (double)ks[c]);
  }
  __syncthreads();
  if (tid < 64) atomicAdd(&g_gram[(b*8+h)*64 + tid], red[tid]);
  else if (tid < 72) atomicAdd(&g_qss[b*64 + h*8 + (tid-64)], red[tid]);
  else if (tid < 80) atomicAdd(&g_kss[b*64 + h*8 + (tid-72)], red[tid]);
}

// ------------------------------- k_attn -------------------------------
__global__ void k_attn(const float* __restrict__ temp, const float* __restrict__ scales)
{
  int t = threadIdx.x;
  if (t >= 32) return;
  int b = t >> 3, h = t & 7;
  float scl = scales[0] + scales[1] + scales[2] + scales[3];
  float T   = temp[h];
  float kd  = g_kdyn;
  float nq[8], nk[8];
  #pragma unroll
  for (int c=0;c<8;c++){
    nq[c] = fmaxf(sqrtf((float)g_qss[b*64 + h*8 + c]), 1e-12f);
    nk[c] = fmaxf(sqrtf((float)g_kss[b*64 + h*8 + c]), 1e-12f);
  }
  float a[8][8];
  #pragma unroll
  for (int c=0;c<8;c++){
    #pragma unroll
    for (int d=0;d<8;d++)
      a[c][d] = ((float)g_gram[(b*8+h)*64 + c*8 + d]) / (nq[c]*nk[d]) * T;
  }
  #pragma unroll
  for (int c=0;c<8;c++){
    bool keep[8];
    #pragma unroll
    for (int d=0;d<8;d++){
      int r = 0;
      #pragma unroll
      for (int e=0;e<8;e++)
        r += (a[c][e] > a[c][d]) || (a[c][e] == a[c][d] && e < d);
      keep[d] = ((float)r < kd);
    }
    float m = -1e30f;
    #pragma unroll
    for (int d=0;d<8;d++) if (keep[d]) m = fmaxf(m, a[c][d]);
    float pr[8]; float sum = 0.f;
    #pragma unroll
    for (int d=0;d<8;d++){ pr[d] = keep[d] ? __expf(a[c][d]-m) : 0.f; sum += pr[d]; }
    float inv = scl / sum;
    #pragma unroll
    for (int d=0;d<8;d++) g_attnw[((b*8+h)*8 + c)*8 + d] = pr[d]*inv;
  }
}

// ------------------------------- k_final -------------------------------
#define FN_WPOUT 0
#define FN_WPOST (16384)
#define FN_FUSED (20480)
#define FN_XS    (28672)
#define FN_VB    (32768)
#define FN_W     (36864)
#define FN_CW    (37376)
#define FN_THR   (37440)
#define FN_TOTAL (37448)

__global__ void __launch_bounds__(256) k_final(
    const float* __restrict__ sw, const float* __restrict__ sb,
    const float* __restrict__ post_b, float* __restrict__ out)
{
  extern __shared__ float sm[];
  float* wpout = sm + FN_WPOUT;
  float* wpost = sm + FN_WPOST;
  float* fused = sm + FN_FUSED;
  float* xs    = sm + FN_XS;
  float* vb    = sm + FN_VB;
  float* W_s   = sm + FN_W;
  float* cw_s  = sm + FN_CW;
  float* thr_s = sm + FN_THR;

  int tid = threadIdx.x;
  int b   = blockIdx.x >> 10;
  int pb  = (blockIdx.x & 1023) << 6;
  int tx = tid & 31, ty = tid >> 5;
  int p0 = ty << 3;

  for (int i=tid; i<4096; i+=256) ((float4*)wpout)[i] = ((const float4*)g_poutT)[i];
  for (int i=tid; i<1024; i+=256) ((float4*)wpost)[i] = ((const float4*)g_postT)[i];
  for (int i=tid; i<512;  i+=256) W_s[i]   = g_attnw[b*512 + i];
  if (tid < 64) cw_s[tid] = g_cw[b*64 + tid];
  if (tid < 8)  thr_s[tid] = (float)(g_resp_sum[b*8 + tid] * (1.0/524288.0));
  {
    const float* xp  = g_xpre + (size_t)b*64*HW + pb;
    const float* lbp = g_lb   + (size_t)b*64*HW + pb;
    for (int i=tid; i<64*16; i+=256){
      int ch=i>>4, q=i&15;
      ((float4*)(xs + ch*64))[q] = __ldg((const float4*)(xp  + (size_t)ch*HW) + q);
      ((float4*)(vb + ch*64))[q] = __ldg((const float4*)(lbp + (size_t)ch*HW) + q);
    }
  }
  __syncthreads();

  // mask in place (same group_resp as k_thr)
  {
    int p  = tid & 63;
    int g0 = (tid >> 6) << 1;
    #pragma unroll
    for (int gi=0; gi<2; gi++){
      int g = g0 + gi;
      float xv[8], resp[8], sw8[8];
      #pragma unroll
      for (int c=0;c<8;c++){ xv[c] = xs[(g*8+c)*64 + p]; sw8[c] = __ldg(sw + g*8 + c); }
      group_resp(xv, cw_s + g*8, sw8, __ldg(sb + g), resp);
      float thr = thr_s[g];
      #pragma unroll
      for (int c=0;c<8;c++){
        float m = resp[c] > thr ? 1.f : resp[c];
        xs[(g*8+c)*64 + p] = xv[c]*m;
      }
    }
  }
  __syncthreads();

  // post conv + bias + residual -> fused rows 64..127 (f32x2)
  {
    u64 acc[2][4];
    #pragma unroll
    for (int i=0;i<2;i++){
      #pragma unroll
      for (int j=0;j<4;j++) acc[i][j]=0ull;
    }
    #pragma unroll 4
    for (int k=0;k<64;k++){
      float2 w  = *((const float2*)(wpost + k*64) + tx);
      float4 a0 = *((const float4*)(xs + k*64) + (ty<<1));
      float4 a1 = *((const float4*)(xs + k*64) + (ty<<1) + 1);
      u64 xp[4] = {pk2(a0.x,a0.y), pk2(a0.z,a0.w), pk2(a1.x,a1.y), pk2(a1.z,a1.w)};
      u64 wp0 = pk2(w.x,w.x), wp1 = pk2(w.y,w.y);
      #pragma unroll
      for (int j=0;j<4;j++){ fma2(acc[0][j],wp0,xp[j]); fma2(acc[1][j],wp1,xp[j]); }
    }
    int o0 = tx<<1;
    float bb0 = __ldg(post_b + o0), bb1 = __ldg(post_b + o0 + 1);
    #pragma unroll
    for (int j=0;j<4;j++){
      float2 v0 = upk2(acc[0][j]);
      float2 v1 = upk2(acc[1][j]);
      float2 r0 = {v0.x + bb0 + vb[o0*64     + p0 + 2*j],
                   v0.y + bb0 + vb[o0*64     + p0 + 2*j+1]};
      float2 r1 = {v1.x + bb1 + vb[(o0+1)*64 + p0 + 2*j],
                   v1.y + bb1 + vb[(o0+1)*64 + p0 + 2*j+1]};
      *((float2*)(fused + (64+o0)*64   + p0 + 2*j)) = r0;
      *((float2*)(fused + (64+o0+1)*64 + p0 + 2*j)) = r1;
    }
  }
  __syncthreads();

  // load v tile (dwconv'd), attn mix -> fused rows 0..63
  {
    const float* vp = g_qkvd + (size_t)(b*192 + 128)*HW + pb;
    for (int i=tid; i<64*16; i+=256){
      int ch=i>>4, q=i&15;
      ((float4*)(vb + ch*64))[q] = __ldg((const float4*)(vp + (size_t)ch*HW) + q);
    }
  }
  __syncthreads();
  {
    int o0 = tx<<1;
    #pragma unroll
    for (int i=0;i<2;i++){
      int o = o0 + i, h = o>>3, ci = o&7;
      u64 acc[4];
      #pragma unroll
      for (int j=0;j<4;j++) acc[j]=0ull;
      #pragma unroll
      for (int d=0;d<8;d++){
        float w = W_s[(h*8+ci)*8 + d];
        u64 wp = pk2(w,w);
        float4 v0 = *((const float4*)(vb + (h*8+d)*64) + (ty<<1));
        float4 v1 = *((const float4*)(vb + (h*8+d)*64) + (ty<<1) + 1);
        fma2(acc[0], wp, pk2(v0.x,v0.y));
        fma2(acc[1], wp, pk2(v0.z,v0.w));
        fma2(acc[2], wp, pk2(v1.x,v1.y));
        fma2(acc[3], wp, pk2(v1.z,v1.w));
      }
      #pragma unroll
      for (int j=0;j<4;j++){
        float2 v = upk2(acc[j]);
        *((float2*)(fused + o*64 + p0 + 2*j)) = v;
      }
    }
  }
  __syncthreads();

  // proj_out GEMM 128x64, K=128 (f32x2)
  {
    u64 acc[4][4];
    #pragma unroll
    for (int i=0;i<4;i++){
      #pragma unroll
      for (int j=0;j<4;j++) acc[i][j]=0ull;
    }
    #pragma unroll 4
    for (int k=0;k<128;k++){
      float4 w  = *((const float4*)(wpout + k*128) + tx);
      float4 a0 = *((const float4*)(fused + k*64) + (ty<<1));
      float4 a1 = *((const float4*)(fused + k*64) + (ty<<1) + 1);
      u64 xp[4] = {pk2(a0.x,a0.y), pk2(a0.z,a0.w), pk2(a1.x,a1.y), pk2(a1.z,a1.w)};
      u64 wp;
      wp = pk2(w.x,w.x);
      fma2(acc[0][0],wp,xp[0]); fma2(acc[0][1],wp,xp[1]); fma2(acc[0][2],wp,xp[2]); fma2(acc[0][3],wp,xp[3]);
      wp = pk2(w.y,w.y);
      fma2(acc[1][0],wp,xp[0]); fma2(acc[1][1],wp,xp[1]); fma2(acc[1][2],wp,xp[2]); fma2(acc[1][3],wp,xp[3]);
      wp = pk2(w.z,w.z);
      fma2(acc[2][0],wp,xp[0]); fma2(acc[2][1],wp,xp[1]); fma2(acc[2][2],wp,xp[2]); fma2(acc[2][3],wp,xp[3]);
      wp = pk2(w.w,w.w);
      fma2(acc[3][0],wp,xp[0]); fma2(acc[3][1],wp,xp[1]); fma2(acc[3][2],wp,xp[2]); fma2(acc[3][3],wp,xp[3]);
    }
    __syncthreads();   // all reads of fused complete
    int o0 = tx<<2;
    #pragma unroll
    for (int i=0;i<4;i++){
      #pragma unroll
      for (int j=0;j<4;j++){
        float2 v = upk2(acc[i][j]);
        *((float2*)(fused + (o0+i)*64 + p0 + 2*j)) = v;
      }
    }
  }
  __syncthreads();
  {
    float* op = out + (size_t)b*128*HW + pb;
    for (int i=tid; i<128*16; i+=256){
      int ch=i>>4, q=i&15;
      *((float4*)(op + (size_t)ch*HW) + q) = *((const float4*)(fused + ch*64) + q);
    }
  }
}

// ------------------------------- launch -------------------------------
extern "C" void kernel_launch(void* const* d_in, const int* in_sizes, int n_in,
                              void* d_out, int out_size)
{
  const float* x      = (const float*)d_in[0];
  const float* projw  = (const float*)d_in[1];
  const float* prew   = (const float*)d_in[2];
  const float* preb   = (const float*)d_in[3];
  const float* w1     = (const float*)d_in[4];
  const float* b1     = (const float*)d_in[5];
  const float* w2     = (const float*)d_in[6];
  const float* b2     = (const float*)d_in[7];
  const float* sw     = (const float*)d_in[8];
  const float* sb     = (const float*)d_in[9];
  const float* postw  = (const float*)d_in[10];
  const float* postb  = (const float*)d_in[11];
  const float* qkvw   = (const float*)d_in[12];
  const float* dww    = (const float*)d_in[13];
  const float* gw1    = (const float*)d_in[14];
  const float* gb1    = (const float*)d_in[15];
  const float* gw2    = (const float*)d_in[16];
  const float* gb2    = (const float*)d_in[17];
  const float* temp   = (const float*)d_in[18];
  const float* scales = (const float*)d_in[19];
  const float* poutw  = (const float*)d_in[20];
  float* out = (float*)d_out;

  cudaFuncSetAttribute(k_front, cudaFuncAttributeMaxDynamicSharedMemorySize, FR_TOTAL*4);
  cudaFuncSetAttribute(k_final, cudaFuncAttributeMaxDynamicSharedMemorySize, FN_TOTAL*4);

  k_prep <<<64, 256>>>(projw, prew, qkvw, gw1, postw, poutw);
  k_front<<<4096, 256, FR_TOTAL*4>>>(x, preb, gb1, gw2, gb2);
  k_dw   <<<768*64, 256>>>(dww);
  k_small<<<1, 32>>>(w1, b1, w2, b2);
  k_thr  <<<256, 256>>>(sw, sb);
  k_gram <<<256, 256>>>();
  k_attn <<<1, 32>>>(temp, scales);
  k_final<<<4096, 256, FN_TOTAL*4>>>(sw, sb, postb, out);
}

// round 5
// speedup vs baseline: 1.9606x; 1.4582x over previous
#include <cuda_runtime.h>

#define HW 65536
#define IMW 256

// ------------------------- device scratch (no allocations) -------------------------
static __device__ __align__(16) float g_projT[128*128];
static __device__ __align__(16) float g_preT [64*64];
static __device__ __align__(16) float g_qkvT [64*192];
static __device__ __align__(16) float g_g1T  [64*32];
static __device__ __align__(16) float g_postT[64*64];
static __device__ __align__(16) float g_poutT[128*128];

static __device__ __align__(16) float g_lb  [(size_t)4*64*HW];   // local branch residual
static __device__ __align__(16) float g_gb  [(size_t)4*64*HW];   // global branch
static __device__ __align__(16) float g_xpre[(size_t)4*64*HW];   // lgce pre-conv output
static __device__ __align__(16) float g_qkv [(size_t)4*192*HW];  // qkv before dwconv
static __device__ __align__(16) float g_qkvd[(size_t)4*192*HW];  // dwconv'd (v only used)

static __device__ double g_pooled[4*64];
static __device__ double g_gate_sum;
static __device__ double g_resp_sum[4*8];
static __device__ double g_gram[4*8*64];
static __device__ double g_qss[4*64];
static __device__ double g_kss[4*64];
static __device__ float  g_cw[4*64];
static __device__ float  g_kdyn;
static __device__ float  g_attnw[4*8*64];

__device__ __forceinline__ float sigm(float v){ return 1.0f/(1.0f + __expf(-v)); }

// ---- packed f32x2 helpers (SASS FFMA2; ptxas never emits it from C++) ----
typedef unsigned long long u64;
__device__ __forceinline__ u64 pk2(float lo, float hi){
  u64 r; asm("mov.b64 %0, {%1,%2};" : "=l"(r) : "f"(lo), "f"(hi)); return r;
}
__device__ __forceinline__ void fma2(u64 &d, u64 a, u64 b){
  asm("fma.rn.f32x2 %0, %1, %2, %0;" : "+l"(d) : "l"(a), "l"(b));
}
__device__ __forceinline__ float2 upk2(u64 v){
  float2 f; asm("mov.b64 {%0,%1}, %2;" : "=f"(f.x), "=f"(f.y) : "l"(v)); return f;
}

// Shared CBAM response path: MUST be identical in k_thr and k_final so that
// resp vs threshold comparisons are bit-consistent across kernels.
__device__ __forceinline__ void group_resp(const float* xv, const float* cw8,
                                           const float* sw8, float sbg, float* resp)
{
  float xc[8]; float dot = sbg;
  #pragma unroll
  for (int c=0;c<8;c++){ xc[c] = xv[c]*cw8[c]; dot = fmaf(xc[c], sw8[c], dot); }
  float sp = sigm(dot);
  #pragma unroll
  for (int c=0;c<8;c++) resp[c] = sigm(xc[c]*sp);
}

// ------------------------------- k_prep -------------------------------
__global__ void k_prep(const float* __restrict__ pw, const float* __restrict__ prew,
                       const float* __restrict__ qw, const float* __restrict__ g1,
                       const float* __restrict__ postw, const float* __restrict__ poutw)
{
  int t = blockIdx.x*256 + threadIdx.x;
  int nt = gridDim.x*256;
  for (int i=t; i<128*128; i+=nt){ int o=i>>7, c=i&127; g_projT[c*128+o]=pw[i]; g_poutT[c*128+o]=poutw[i]; }
  for (int i=t; i<64*64;  i+=nt){ int o=i>>6, c=i&63;  g_preT[c*64+o]=prew[i]; g_postT[c*64+o]=postw[i]; }
  for (int i=t; i<192*64; i+=nt){ int o=i/64, c=i%64;  g_qkvT[c*192+o]=qw[i]; }
  for (int i=t; i<32*64;  i+=nt){ int o=i>>6, c=i&63;  g_g1T[c*32+o]=g1[i]; }
  if (t < 256){ g_pooled[t]=0.0; g_qss[t]=0.0; g_kss[t]=0.0; }
  for (int i=t; i<2048; i+=nt) g_gram[i]=0.0;
  if (t < 32) g_resp_sum[t]=0.0;
  if (t == 0) g_gate_sum=0.0;
}

// ------------------------------- kf_A: input_proj -------------------------------
// smem: wsP[128*128] + xs[128*68]  (stride-68 pad kills store bank conflicts)
#define FA_XS  16384
#define FA_TOT (16384 + 128*68)   // 25088 floats

__global__ void __launch_bounds__(256) kf_A(const float* __restrict__ x)
{
  extern __shared__ float sm[];
  float* wsP = sm;
  float* xs  = sm + FA_XS;
  int tid = threadIdx.x;
  int b   = blockIdx.x >> 10;
  int pb  = (blockIdx.x & 1023) << 6;
  int tx = tid & 31, ty = tid >> 5;
  int p0 = ty << 3;

  for (int i=tid; i<128*32; i+=256) ((float4*)wsP)[i] = ((const float4*)g_projT)[i];
  const float* xb = x + (size_t)b*128*HW + pb;
  for (int i=tid; i<128*16; i+=256){
    int ch = i>>4, p4 = i&15;
    ((float4*)(xs + ch*68))[p4] = __ldg((const float4*)(xb + (size_t)ch*HW) + p4);
  }
  __syncthreads();

  u64 acc[4][4];
  #pragma unroll
  for (int i=0;i<4;i++){
    #pragma unroll
    for (int j=0;j<4;j++) acc[i][j]=0ull;
  }
  #pragma unroll 4
  for (int k=0;k<128;k++){
    float4 w  = *((const float4*)(wsP + k*128) + tx);
    float4 a0 = *((const float4*)(xs + k*68) + (ty<<1));
    float4 a1 = *((const float4*)(xs + k*68) + (ty<<1) + 1);
    u64 xp[4] = {pk2(a0.x,a0.y), pk2(a0.z,a0.w), pk2(a1.x,a1.y), pk2(a1.z,a1.w)};
    u64 wp;
    wp = pk2(w.x,w.x);
    fma2(acc[0][0],wp,xp[0]); fma2(acc[0][1],wp,xp[1]); fma2(acc[0][2],wp,xp[2]); fma2(acc[0][3],wp,xp[3]);
    wp = pk2(w.y,w.y);
    fma2(acc[1][0],wp,xp[0]); fma2(acc[1][1],wp,xp[1]); fma2(acc[1][2],wp,xp[2]); fma2(acc[1][3],wp,xp[3]);
    wp = pk2(w.z,w.z);
    fma2(acc[2][0],wp,xp[0]); fma2(acc[2][1],wp,xp[1]); fma2(acc[2][2],wp,xp[2]); fma2(acc[2][3],wp,xp[3]);
    wp = pk2(w.w,w.w);
    fma2(acc[3][0],wp,xp[0]); fma2(acc[3][1],wp,xp[1]); fma2(acc[3][2],wp,xp[2]); fma2(acc[3][3],wp,xp[3]);
  }
  __syncthreads();   // all xs reads done -> safe to overwrite in place
  int o0 = tx<<2;
  #pragma unroll
  for (int i=0;i<4;i++){
    #pragma unroll
    for (int j=0;j<4;j++){
      float2 v = upk2(acc[i][j]);
      *((float2*)(xs + (o0+i)*68 + p0 + 2*j)) = v;
    }
  }
  __syncthreads();
  float* lbp = g_lb + (size_t)b*64*HW + pb;
  float* gbp = g_gb + (size_t)b*64*HW + pb;
  for (int i=tid; i<64*16; i+=256){
    int ch=i>>4, q=i&15;
    *((float4*)(lbp + (size_t)ch*HW) + q) = ((const float4*)(xs + ch*68))[q];
    *((float4*)(gbp + (size_t)ch*HW) + q) = ((const float4*)(xs + (64+ch)*68))[q];
  }
}

// ------------------------------- kf_B: qkv + gate -------------------------------
#define FB_WQ  0
#define FB_WG  12288
#define FB_XG  14336
#define FB_ST  (14336 + 64*68)            // 18688
#define FB_HID (18688 + 64*68)            // 23040
#define FB_TOT (23040 + 64*33)            // 25152 floats

__global__ void __launch_bounds__(256) kf_B(
    const float* __restrict__ gate_b1, const float* __restrict__ gate_w2,
    const float* __restrict__ gate_b2)
{
  extern __shared__ float sm[];
  float* wsQ  = sm + FB_WQ;
  float* wsG  = sm + FB_WG;
  float* xg   = sm + FB_XG;
  float* stg  = sm + FB_ST;
  float* hid  = sm + FB_HID;
  int tid = threadIdx.x;
  int b   = blockIdx.x >> 10;
  int pb  = (blockIdx.x & 1023) << 6;
  int tx = tid & 31, ty = tid >> 5;
  int p0 = ty << 3;

  for (int i=tid; i<64*48; i+=256) ((float4*)wsQ)[i] = ((const float4*)g_qkvT)[i];
  for (int i=tid; i<64*8;  i+=256) ((float4*)wsG)[i] = ((const float4*)g_g1T)[i];
  const float* gbp = g_gb + (size_t)b*64*HW + pb;
  for (int i=tid; i<64*16; i+=256){
    int ch=i>>4, q=i&15;
    ((float4*)(xg + ch*68))[q] = __ldg((const float4*)(gbp + (size_t)ch*HW) + q);
  }
  __syncthreads();

  // gate hidden (32 x 64px, K=64)
  {
    int o0 = (tid & 3) << 3;
    int p  = tid >> 2;
    u64 acc[4];
    #pragma unroll
    for (int i=0;i<4;i++) acc[i]=0ull;
    #pragma unroll 4
    for (int k=0;k<64;k++){
      float xv = xg[k*68 + p];
      u64 xp = pk2(xv,xv);
      float4 w0 = *((const float4*)(wsG + k*32 + o0));
      float4 w1 = *((const float4*)(wsG + k*32 + o0) + 1);
      fma2(acc[0], pk2(w0.x,w0.y), xp);
      fma2(acc[1], pk2(w0.z,w0.w), xp);
      fma2(acc[2], pk2(w1.x,w1.y), xp);
      fma2(acc[3], pk2(w1.z,w1.w), xp);
    }
    #pragma unroll
    for (int i=0;i<4;i++){
      float2 v = upk2(acc[i]);
      hid[p*33 + o0 + 2*i]     = fmaxf(v.x + __ldg(gate_b1 + o0 + 2*i), 0.f);
      hid[p*33 + o0 + 2*i + 1] = fmaxf(v.y + __ldg(gate_b1 + o0 + 2*i + 1), 0.f);
    }
  }
  __syncthreads();

  // qkv conv: outputs o = i*32 + tx (i=0..5)
  u64 acc[6][4];
  #pragma unroll
  for (int i=0;i<6;i++){
    #pragma unroll
    for (int j=0;j<4;j++) acc[i][j]=0ull;
  }
  #pragma unroll 2
  for (int k=0;k<64;k++){
    float4 a0 = *((const float4*)(xg + k*68) + (ty<<1));
    float4 a1 = *((const float4*)(xg + k*68) + (ty<<1) + 1);
    u64 xp[4] = {pk2(a0.x,a0.y), pk2(a0.z,a0.w), pk2(a1.x,a1.y), pk2(a1.z,a1.w)};
    #pragma unroll
    for (int i=0;i<6;i++){
      float w = wsQ[k*192 + i*32 + tx];
      u64 wp = pk2(w,w);
      #pragma unroll
      for (int j=0;j<4;j++) fma2(acc[i][j],wp,xp[j]);
    }
  }

  // gate scalar per pixel + global fp64 sum (hid complete; guarded by sync above
  // plus the barrier at the end of the qkv staging isn't needed: hid was synced)
  if (tid < 64){
    float g = __ldg(gate_b2);
    #pragma unroll
    for (int h=0;h<32;h++) g = fmaf(hid[tid*33+h], __ldg(gate_w2+h), g);
    g = sigm(g);
    #pragma unroll
    for (int off=16; off; off>>=1) g += __shfl_down_sync(0xffffffffu, g, off);
    if ((tid&31)==0) atomicAdd(&g_gate_sum, (double)g);
  }

  // 3 staging waves of 64 channels each
  float* qp = g_qkv + (size_t)b*192*HW + pb;
  #pragma unroll
  for (int w=0; w<3; w++){
    __syncthreads();
    #pragma unroll
    for (int e=0; e<2; e++){
      int i = 2*w + e;
      int lc = e*32 + tx;
      #pragma unroll
      for (int j=0;j<4;j++){
        float2 v = upk2(acc[i][j]);
        *((float2*)(stg + lc*68 + p0 + 2*j)) = v;
      }
    }
    __syncthreads();
    for (int t=tid; t<64*16; t+=256){
      int ch=t>>4, q=t&15;
      *((float4*)(qp + (size_t)(w*64+ch)*HW) + q) = ((const float4*)(stg + ch*68))[q];
    }
  }
}

// ------------------------------- kf_C: lgce pre conv -------------------------------
#define FC_XL  4096
#define FC_SP  (4096 + 64*68)   // 8448
#define FC_TOT (8448 + 512)     // 8960 floats

__global__ void __launch_bounds__(256) kf_C(const float* __restrict__ pre_b)
{
  extern __shared__ float sm[];
  float* wsE  = sm;
  float* xl   = sm + FC_XL;
  float* spool= sm + FC_SP;
  int tid = threadIdx.x;
  int b   = blockIdx.x >> 10;
  int pb  = (blockIdx.x & 1023) << 6;
  int tx = tid & 31, ty = tid >> 5;
  int p0 = ty << 3;

  for (int i=tid; i<64*16; i+=256) ((float4*)wsE)[i] = ((const float4*)g_preT)[i];
  const float* lbp = g_lb + (size_t)b*64*HW + pb;
  for (int i=tid; i<64*16; i+=256){
    int ch=i>>4, q=i&15;
    ((float4*)(xl + ch*68))[q] = __ldg((const float4*)(lbp + (size_t)ch*HW) + q);
  }
  __syncthreads();

  u64 acc[2][4];
  #pragma unroll
  for (int i=0;i<2;i++){
    #pragma unroll
    for (int j=0;j<4;j++) acc[i][j]=0ull;
  }
  #pragma unroll 4
  for (int k=0;k<64;k++){
    float2 w  = *((const float2*)(wsE + k*64) + tx);
    float4 a0 = *((const float4*)(xl + k*68) + (ty<<1));
    float4 a1 = *((const float4*)(xl + k*68) + (ty<<1) + 1);
    u64 xp[4] = {pk2(a0.x,a0.y), pk2(a0.z,a0.w), pk2(a1.x,a1.y), pk2(a1.z,a1.w)};
    u64 wp0 = pk2(w.x,w.x), wp1 = pk2(w.y,w.y);
    #pragma unroll
    for (int j=0;j<4;j++){ fma2(acc[0][j],wp0,xp[j]); fma2(acc[1][j],wp1,xp[j]); }
  }
  __syncthreads();   // all xl reads done
  int o0 = tx<<1;
  float bb0 = __ldg(pre_b + o0), bb1 = __ldg(pre_b + o0 + 1);
  float ps0 = 0.f, ps1 = 0.f;
  #pragma unroll
  for (int j=0;j<4;j++){
    float2 v0 = upk2(acc[0][j]);
    float2 v1 = upk2(acc[1][j]);
    float2 r0 = {v0.x + bb0, v0.y + bb0};
    float2 r1 = {v1.x + bb1, v1.y + bb1};
    ps0 += r0.x + r0.y; ps1 += r1.x + r1.y;
    *((float2*)(xl + o0*68     + p0 + 2*j)) = r0;
    *((float2*)(xl + (o0+1)*68 + p0 + 2*j)) = r1;
  }
  spool[o0*8 + ty]     = ps0;
  spool[(o0+1)*8 + ty] = ps1;
  __syncthreads();
  if (tid < 64){
    float s = 0.f;
    #pragma unroll
    for (int t2=0;t2<8;t2++) s += spool[tid*8 + t2];
    atomicAdd(&g_pooled[b*64 + tid], (double)s);
  }
  float* xp = g_xpre + (size_t)b*64*HW + pb;
  for (int i=tid; i<64*16; i+=256){
    int ch=i>>4, q=i&15;
    *((float4*)(xp + (size_t)ch*HW) + q) = ((const float4*)(xl + ch*68))[q];
  }
}

// ------------------------------- k_dw: depthwise 3x3 SAME, V ONLY -------------------------------
__global__ void __launch_bounds__(256) k_dw(const float* __restrict__ dww)
{
  int bid = blockIdx.x;                 // 256 * 64
  int bcv = bid >> 6;                   // b*64 + cv
  int bb  = bcv >> 6, cv = bcv & 63;
  int ch  = 128 + cv;
  int y   = ((bid & 63) << 2) + (threadIdx.x >> 6);
  int xq  = (threadIdx.x & 63) << 2;
  float w[9];
  #pragma unroll
  for (int i=0;i<9;i++) w[i] = __ldg(dww + ch*9 + i);
  const float* img = g_qkv + (size_t)(bb*192 + ch)*HW;
  float v[3][6];
  #pragma unroll
  for (int r=0;r<3;r++){
    int yy = y - 1 + r;
    if ((unsigned)yy < 256u){
      float4 c4 = __ldg((const float4*)(img + yy*IMW + xq));
      v[r][1]=c4.x; v[r][2]=c4.y; v[r][3]=c4.z; v[r][4]=c4.w;
      v[r][0] = (xq > 0)   ? __ldg(img + yy*IMW + xq - 1) : 0.f;
      v[r][5] = (xq < 252) ? __ldg(img + yy*IMW + xq + 4) : 0.f;
    } else {
      #pragma unroll
      for (int j=0;j<6;j++) v[r][j]=0.f;
    }
  }
  float o[4];
  #pragma unroll
  for (int j=0;j<4;j++){
    float s=0.f;
    #pragma unroll
    for (int r=0;r<3;r++){
      s = fmaf(v[r][j],   w[r*3+0], s);
      s = fmaf(v[r][j+1], w[r*3+1], s);
      s = fmaf(v[r][j+2], w[r*3+2], s);
    }
    o[j]=s;
  }
  float4 ov = {o[0],o[1],o[2],o[3]};
  *((float4*)(g_qkvd + (size_t)(bb*192 + ch)*HW + y*IMW + xq)) = ov;
}

// ------------------------------- k_small: cw + kdyn -------------------------------
__global__ void k_small(const float* __restrict__ w1, const float* __restrict__ b1,
                        const float* __restrict__ w2, const float* __restrict__ b2)
{
  int t = threadIdx.x;
  if (t < 32){
    int b = t >> 3, g = t & 7;
    float pooled[8];
    #pragma unroll
    for (int c=0;c<8;c++) pooled[c] = (float)(g_pooled[b*64 + g*8 + c] * (1.0/65536.0));
    float h0 = b1[g*2+0], h1 = b1[g*2+1];
    #pragma unroll
    for (int c=0;c<8;c++){
      h0 = fmaf(pooled[c], w1[g*16 + 0*8 + c], h0);
      h1 = fmaf(pooled[c], w1[g*16 + 1*8 + c], h1);
    }
    h0 = fmaxf(h0, 0.f); h1 = fmaxf(h1, 0.f);
    #pragma unroll
    for (int c=0;c<8;c++){
      float v = b2[g*8+c];
      v = fmaf(h0, w2[g*16 + c*2 + 0], v);
      v = fmaf(h1, w2[g*16 + c*2 + 1], v);
      g_cw[b*64 + g*8 + c] = sigm(v);
    }
    if (t == 0){
      float mean = (float)(g_gate_sum * (1.0/262144.0));
      g_kdyn = fminf(fmaxf(floorf(8.f*mean), 1.f), 8.f);
    }
  }
}

// ------------------------------- k_thr: resp threshold sums (4px/thread) -------------------------------
__global__ void __launch_bounds__(256) k_thr(const float* __restrict__ sw, const float* __restrict__ sb)
{
  __shared__ float cw_s[64], sw_s[64], sb_s[8];
  __shared__ float ssum[8];
  int tid = threadIdx.x;
  int b = blockIdx.x >> 6;
  int p = ((blockIdx.x & 63) << 10) + tid*4;
  if (tid < 64){ cw_s[tid] = g_cw[b*64 + tid]; sw_s[tid] = __ldg(sw + tid); }
  if (tid < 8){ sb_s[tid] = __ldg(sb + tid); ssum[tid] = 0.f; }
  __syncthreads();
  const float* xp = g_xpre + (size_t)b*64*HW + p;
  #pragma unroll
  for (int g=0; g<8; g++){
    float4 xv4[8];
    #pragma unroll
    for (int c=0;c<8;c++) xv4[c] = __ldg((const float4*)(xp + (size_t)(g*8+c)*HW));
    float s = 0.f;
    #pragma unroll
    for (int px=0; px<4; px++){
      float xv[8], resp[8];
      #pragma unroll
      for (int c=0;c<8;c++) xv[c] = ((const float*)&xv4[c])[px];
      group_resp(xv, cw_s + g*8, sw_s + g*8, sb_s[g], resp);
      #pragma unroll
      for (int c=0;c<8;c++) s += resp[c];
    }
    #pragma unroll
    for (int off=16; off; off>>=1) s += __shfl_down_sync(0xffffffffu, s, off);
    if ((tid&31)==0) atomicAdd(&ssum[g], s);
  }
  __syncthreads();
  if (tid < 8) atomicAdd(&g_resp_sum[b*8 + tid], (double)ssum[tid]);
}

// ------------------------------- k_gram: fused dwconv(q,k) + Gram -------------------------------
// grid = 4(b) * 8(h) * 16(row groups of 16 rows) = 512 blocks, 256 threads
#define GR_SQ  0
#define GR_SK  12288
#define GR_WD  24576
#define GR_RED 24736
#define GR_TOT (24736 + 640)    // 25376 floats

__global__ void __launch_bounds__(256) k_gram(const float* __restrict__ dww)
{
  extern __shared__ float sm[];
  float* sQ  = sm + GR_SQ;    // 8ch x 6rows x 256
  float* sK  = sm + GR_SK;
  float* wdw = sm + GR_WD;    // 16 x 9
  float* wred= sm + GR_RED;   // 8 warps x 80
  int tid = threadIdx.x;
  int b  = blockIdx.x >> 7;
  int h  = (blockIdx.x >> 4) & 7;
  int rb = blockIdx.x & 15;

  if (tid < 144){
    int c = tid/9, j = tid%9;
    int ch = (c<8) ? (h*8+c) : (64 + h*8 + (c-8));
    wdw[tid] = __ldg(dww + ch*9 + j);
  }

  float gr[8][8], qs[8], ks[8];
  #pragma unroll
  for (int c=0;c<8;c++){
    qs[c]=0.f; ks[c]=0.f;
    #pragma unroll
    for (int d=0;d<8;d++) gr[c][d]=0.f;
  }
  int r_l = tid >> 6;           // 0..3
  int xq  = (tid & 63) << 2;

  for (int sg=0; sg<4; sg++){
    int gr0 = rb*16 + sg*4;
    __syncthreads();            // prior compute reads done
    for (int i=tid; i<6144; i+=256){
      int f4 = i & 63;
      int rr = (i >> 6) % 6;
      int c  = i / 384;
      int row = gr0 - 1 + rr;
      float4 v = {0.f,0.f,0.f,0.f};
      int ch = (c<8) ? (h*8+c) : (64 + h*8 + (c-8));
      if ((unsigned)row < 256u)
        v = __ldg((const float4*)(g_qkv + (size_t)(b*192+ch)*HW + row*IMW) + f4);
      float* dst = (c<8) ? (sQ + c*1536 + rr*256) : (sK + (c-8)*1536 + rr*256);
      ((float4*)dst)[f4] = v;
    }
    __syncthreads();
    #pragma unroll
    for (int px=0; px<4; px++){
      int col = xq + px;
      bool lok = (col > 0), rok = (col < 255);
      float q[8], k[8];
      #pragma unroll
      for (int c=0;c<8;c++){
        const float* pq = sQ + c*1536 + r_l*256 + col;
        const float* pk = sK + c*1536 + r_l*256 + col;
        const float* wq = wdw + c*9;
        const float* wk = wdw + 72 + c*9;
        float aq=0.f, ak=0.f;
        #pragma unroll
        for (int rr=0;rr<3;rr++){
          float lq = lok ? pq[rr*256-1] : 0.f;
          float cq = pq[rr*256];
          float rq = rok ? pq[rr*256+1] : 0.f;
          aq = fmaf(lq, wq[rr*3+0], aq);
          aq = fmaf(cq, wq[rr*3+1], aq);
          aq = fmaf(rq, wq[rr*3+2], aq);
          float lk = lok ? pk[rr*256-1] : 0.f;
          float ck = pk[rr*256];
          float rk = rok ? pk[rr*256+1] : 0.f;
          ak = fmaf(lk, wk[rr*3+0], ak);
          ak = fmaf(ck, wk[rr*3+1], ak);
          ak = fmaf(rk, wk[rr*3+2], ak);
        }
        q[c]=aq; k[c]=ak;
      }
      #pragma unroll
      for (int c=0;c<8;c++){
        qs[c]=fmaf(q[c],q[c],qs[c]); ks[c]=fmaf(k[c],k[c],ks[c]);
        #pragma unroll
        for (int d=0;d<8;d++) gr[c][d]=fmaf(q[c],k[d],gr[c][d]);
      }
    }
  }

  // warp shuffle reduce -> smem -> 80 global fp64 atomics per block
  int lane = tid & 31, wd = tid >> 5;
  #pragma unroll
  for (int c=0;c<8;c++){
    #pragma unroll
    for (int d=0;d<8;d++){
      float v = gr[c][d];
      #pragma unroll
      for (int o=16;o;o>>=1) v += __shfl_down_sync(0xffffffffu, v, o);
      if (lane==0) wred[wd*80 + c*8 + d] = v;
    }
  }
  #pragma unroll
  for (int c=0;c<8;c++){
    float v = qs[c];
    #pragma unroll
    for (int o=16;o;o>>=1) v += __shfl_down_sync(0xffffffffu, v, o);
    if (lane==0) wred[wd*80 + 64 + c] = v;
    float u = ks[c];
    #pragma unroll
    for (int o=16;o;o>>=1) u += __shfl_down_sync(0xffffffffu, u, o);
    if (lane==0) wred[wd*80 + 72 + c] = u;
  }
  __syncthreads();
  if (tid < 80){
    float s = 0.f;
    #pragma unroll
    for (int ww=0; ww<8; ww++) s += wred[ww*80 + tid];
    if (tid < 64)      atomicAdd(&g_gram[(b*8+h)*64 + tid], (double)s);
    else if (tid < 72) atomicAdd(&g_qss[b*64 + h*8 + (tid-64)], (double)s);
    else               atomicAdd(&g_kss[b*64 + h*8 + (tid-72)], (double)s);
  }
}

// ------------------------------- k_attn -------------------------------
__global__ void k_attn(const float* __restrict__ temp, const float* __restrict__ scales)
{
  int t = threadIdx.x;
  if (t >= 32) return;
  int b = t >> 3, h = t & 7;
  float scl = scales[0] + scales[1] + scales[2] + scales[3];
  float T   = temp[h];
  float kd  = g_kdyn;
  float nq[8], nk[8];
  #pragma unroll
  for (int c=0;c<8;c++){
    nq[c] = fmaxf(sqrtf((float)g_qss[b*64 + h*8 + c]), 1e-12f);
    nk[c] = fmaxf(sqrtf((float)g_kss[b*64 + h*8 + c]), 1e-12f);
  }
  float a[8][8];
  #pragma unroll
  for (int c=0;c<8;c++){
    #pragma unroll
    for (int d=0;d<8;d++)
      a[c][d] = ((float)g_gram[(b*8+h)*64 + c*8 + d]) / (nq[c]*nk[d]) * T;
  }
  #pragma unroll
  for (int c=0;c<8;c++){
    bool keep[8];
    #pragma unroll
    for (int d=0;d<8;d++){
      int r = 0;
      #pragma unroll
      for (int e=0;e<8;e++)
        r += (a[c][e] > a[c][d]) || (a[c][e] == a[c][d] && e < d);
      keep[d] = ((float)r < kd);
    }
    float m = -1e30f;
    #pragma unroll
    for (int d=0;d<8;d++) if (keep[d]) m = fmaxf(m, a[c][d]);
    float pr[8]; float sum = 0.f;
    #pragma unroll
    for (int d=0;d<8;d++){ pr[d] = keep[d] ? __expf(a[c][d]-m) : 0.f; sum += pr[d]; }
    float inv = scl / sum;
    #pragma unroll
    for (int d=0;d<8;d++) g_attnw[((b*8+h)*8 + c)*8 + d] = pr[d]*inv;
  }
}

// ------------------------------- k_final -------------------------------
#define FN_WPOUT 0
#define FN_WPOST (16384)
#define FN_FUSED (20480)
#define FN_XS    (28672)
#define FN_VB    (32768)
#define FN_W     (36864)
#define FN_CW    (37376)
#define FN_THR   (37440)
#define FN_TOTAL (37448)

__global__ void __launch_bounds__(256) k_final(
    const float* __restrict__ sw, const float* __restrict__ sb,
    const float* __restrict__ post_b, float* __restrict__ out)
{
  extern __shared__ float sm[];
  float* wpout = sm + FN_WPOUT;
  float* wpost = sm + FN_WPOST;
  float* fused = sm + FN_FUSED;
  float* xs    = sm + FN_XS;
  float* vb    = sm + FN_VB;
  float* W_s   = sm + FN_W;
  float* cw_s  = sm + FN_CW;
  float* thr_s = sm + FN_THR;

  int tid = threadIdx.x;
  int b   = blockIdx.x >> 10;
  int pb  = (blockIdx.x & 1023) << 6;
  int tx = tid & 31, ty = tid >> 5;
  int p0 = ty << 3;

  for (int i=tid; i<4096; i+=256) ((float4*)wpout)[i] = ((const float4*)g_poutT)[i];
  for (int i=tid; i<1024; i+=256) ((float4*)wpost)[i] = ((const float4*)g_postT)[i];
  for (int i=tid; i<512;  i+=256) W_s[i]   = g_attnw[b*512 + i];
  if (tid < 64) cw_s[tid] = g_cw[b*64 + tid];
  if (tid < 8)  thr_s[tid] = (float)(g_resp_sum[b*8 + tid] * (1.0/524288.0));
  {
    const float* xp  = g_xpre + (size_t)b*64*HW + pb;
    const float* lbp = g_lb   + (size_t)b*64*HW + pb;
    for (int i=tid; i<64*16; i+=256){
      int ch=i>>4, q=i&15;
      ((float4*)(xs + ch*64))[q] = __ldg((const float4*)(xp  + (size_t)ch*HW) + q);
      ((float4*)(vb + ch*64))[q] = __ldg((const float4*)(lbp + (size_t)ch*HW) + q);
    }
  }
  __syncthreads();

  // mask in place (same group_resp as k_thr)
  {
    int p  = tid & 63;
    int g0 = (tid >> 6) << 1;
    #pragma unroll
    for (int gi=0; gi<2; gi++){
      int g = g0 + gi;
      float xv[8], resp[8], sw8[8];
      #pragma unroll
      for (int c=0;c<8;c++){ xv[c] = xs[(g*8+c)*64 + p]; sw8[c] = __ldg(sw + g*8 + c); }
      group_resp(xv, cw_s + g*8, sw8, __ldg(sb + g), resp);
      float thr = thr_s[g];
      #pragma unroll
      for (int c=0;c<8;c++){
        float m = resp[c] > thr ? 1.f : resp[c];
        xs[(g*8+c)*64 + p] = xv[c]*m;
      }
    }
  }
  __syncthreads();

  // post conv + bias + residual -> fused rows 64..127 (f32x2)
  {
    u64 acc[2][4];
    #pragma unroll
    for (int i=0;i<2;i++){
      #pragma unroll
      for (int j=0;j<4;j++) acc[i][j]=0ull;
    }
    #pragma unroll 4
    for (int k=0;k<64;k++){
      float2 w  = *((const float2*)(wpost + k*64) + tx);
      float4 a0 = *((const float4*)(xs + k*64) + (ty<<1));
      float4 a1 = *((const float4*)(xs + k*64) + (ty<<1) + 1);
      u64 xp[4] = {pk2(a0.x,a0.y), pk2(a0.z,a0.w), pk2(a1.x,a1.y), pk2(a1.z,a1.w)};
      u64 wp0 = pk2(w.x,w.x), wp1 = pk2(w.y,w.y);
      #pragma unroll
      for (int j=0;j<4;j++){ fma2(acc[0][j],wp0,xp[j]); fma2(acc[1][j],wp1,xp[j]); }
    }
    int o0 = tx<<1;
    float bb0 = __ldg(post_b + o0), bb1 = __ldg(post_b + o0 + 1);
    #pragma unroll
    for (int j=0;j<4;j++){
      float2 v0 = upk2(acc[0][j]);
      float2 v1 = upk2(acc[1][j]);
      float2 r0 = {v0.x + bb0 + vb[o0*64     + p0 + 2*j],
                   v0.y + bb0 + vb[o0*64     + p0 + 2*j+1]};
      float2 r1 = {v1.x + bb1 + vb[(o0+1)*64 + p0 + 2*j],
                   v1.y + bb1 + vb[(o0+1)*64 + p0 + 2*j+1]};
      *((float2*)(fused + (64+o0)*64   + p0 + 2*j)) = r0;
      *((float2*)(fused + (64+o0+1)*64 + p0 + 2*j)) = r1;
    }
  }
  __syncthreads();

  // load v tile (dwconv'd), attn mix -> fused rows 0..63
  {
    const float* vp = g_qkvd + (size_t)(b*192 + 128)*HW + pb;
    for (int i=tid; i<64*16; i+=256){
      int ch=i>>4, q=i&15;
      ((float4*)(vb + ch*64))[q] = __ldg((const float4*)(vp + (size_t)ch*HW) + q);
    }
  }
  __syncthreads();
  {
    int o0 = tx<<1;
    #pragma unroll
    for (int i=0;i<2;i++){
      int o = o0 + i, h = o>>3, ci = o&7;
      u64 acc[4];
      #pragma unroll
      for (int j=0;j<4;j++) acc[j]=0ull;
      #pragma unroll
      for (int d=0;d<8;d++){
        float w = W_s[(h*8+ci)*8 + d];
        u64 wp = pk2(w,w);
        float4 v0 = *((const float4*)(vb + (h*8+d)*64) + (ty<<1));
        float4 v1 = *((const float4*)(vb + (h*8+d)*64) + (ty<<1) + 1);
        fma2(acc[0], wp, pk2(v0.x,v0.y));
        fma2(acc[1], wp, pk2(v0.z,v0.w));
        fma2(acc[2], wp, pk2(v1.x,v1.y));
        fma2(acc[3], wp, pk2(v1.z,v1.w));
      }
      #pragma unroll
      for (int j=0;j<4;j++){
        float2 v = upk2(acc[j]);
        *((float2*)(fused + o*64 + p0 + 2*j)) = v;
      }
    }
  }
  __syncthreads();

  // proj_out GEMM 128x64, K=128 (f32x2)
  {
    u64 acc[4][4];
    #pragma unroll
    for (int i=0;i<4;i++){
      #pragma unroll
      for (int j=0;j<4;j++) acc[i][j]=0ull;
    }
    #pragma unroll 4
    for (int k=0;k<128;k++){
      float4 w  = *((const float4*)(wpout + k*128) + tx);
      float4 a0 = *((const float4*)(fused + k*64) + (ty<<1));
      float4 a1 = *((const float4*)(fused + k*64) + (ty<<1) + 1);
      u64 xp[4] = {pk2(a0.x,a0.y), pk2(a0.z,a0.w), pk2(a1.x,a1.y), pk2(a1.z,a1.w)};
      u64 wp;
      wp = pk2(w.x,w.x);
      fma2(acc[0][0],wp,xp[0]); fma2(acc[0][1],wp,xp[1]); fma2(acc[0][2],wp,xp[2]); fma2(acc[0][3],wp,xp[3]);
      wp = pk2(w.y,w.y);
      fma2(acc[1][0],wp,xp[0]); fma2(acc[1][1],wp,xp[1]); fma2(acc[1][2],wp,xp[2]); fma2(acc[1][3],wp,xp[3]);
      wp = pk2(w.z,w.z);
      fma2(acc[2][0],wp,xp[0]); fma2(acc[2][1],wp,xp[1]); fma2(acc[2][2],wp,xp[2]); fma2(acc[2][3],wp,xp[3]);
      wp = pk2(w.w,w.w);
      fma2(acc[3][0],wp,xp[0]); fma2(acc[3][1],wp,xp[1]); fma2(acc[3][2],wp,xp[2]); fma2(acc[3][3],wp,xp[3]);
    }
    __syncthreads();   // all reads of fused complete
    int o0 = tx<<2;
    #pragma unroll
    for (int i=0;i<4;i++){
      #pragma unroll
      for (int j=0;j<4;j++){
        float2 v = upk2(acc[i][j]);
        *((float2*)(fused + (o0+i)*64 + p0 + 2*j)) = v;
      }
    }
  }
  __syncthreads();
  {
    float* op = out + (size_t)b*128*HW + pb;
    for (int i=tid; i<128*16; i+=256){
      int ch=i>>4, q=i&15;
      *((float4*)(op + (size_t)ch*HW) + q) = ((const float4*)(fused + ch*64))[q];
    }
  }
}

// ------------------------------- launch -------------------------------
extern "C" void kernel_launch(void* const* d_in, const int* in_sizes, int n_in,
                              void* d_out, int out_size)
{
  const float* x      = (const float*)d_in[0];
  const float* projw  = (const float*)d_in[1];
  const float* prew   = (const float*)d_in[2];
  const float* preb   = (const float*)d_in[3];
  const float* w1     = (const float*)d_in[4];
  const float* b1     = (const float*)d_in[5];
  const float* w2     = (const float*)d_in[6];
  const float* b2     = (const float*)d_in[7];
  const float* sw     = (const float*)d_in[8];
  const float* sb     = (const float*)d_in[9];
  const float* postw  = (const float*)d_in[10];
  const float* postb  = (const float*)d_in[11];
  const float* qkvw   = (const float*)d_in[12];
  const float* dww    = (const float*)d_in[13];
  const float* gw1    = (const float*)d_in[14];
  const float* gb1    = (const float*)d_in[15];
  const float* gw2    = (const float*)d_in[16];
  const float* gb2    = (const float*)d_in[17];
  const float* temp   = (const float*)d_in[18];
  const float* scales = (const float*)d_in[19];
  const float* poutw  = (const float*)d_in[20];
  float* out = (float*)d_out;

  cudaFuncSetAttribute(kf_A,  cudaFuncAttributeMaxDynamicSharedMemorySize, FA_TOT*4);
  cudaFuncSetAttribute(kf_B,  cudaFuncAttributeMaxDynamicSharedMemorySize, FB_TOT*4);
  cudaFuncSetAttribute(kf_C,  cudaFuncAttributeMaxDynamicSharedMemorySize, FC_TOT*4);
  cudaFuncSetAttribute(k_gram, cudaFuncAttributeMaxDynamicSharedMemorySize, GR_TOT*4);
  cudaFuncSetAttribute(k_final, cudaFuncAttributeMaxDynamicSharedMemorySize, FN_TOTAL*4);

  k_prep <<<64, 256>>>(projw, prew, qkvw, gw1, postw, poutw);
  kf_A  <<<4096, 256, FA_TOT*4>>>(x);
  kf_B  <<<4096, 256, FB_TOT*4>>>(gb1, gw2, gb2);
  kf_C  <<<4096, 256, FC_TOT*4>>>(preb);
  k_dw  <<<256*64, 256>>>(dww);
  k_small<<<1, 32>>>(w1, b1, w2, b2);
  k_thr <<<256, 256>>>(sw, sb);
  k_gram<<<512, 256, GR_TOT*4>>>(dww);
  k_attn<<<1, 32>>>(temp, scales);
  k_final<<<4096, 256, FN_TOTAL*4>>>(sw, sb, postb, out);
}

// round 6
// speedup vs baseline: 2.5900x; 1.3210x over previous
#include <cuda_runtime.h>

#define HW 65536
#define IMW 256

// ------------------------- device scratch (no allocations) -------------------------
static __device__ __align__(16) float g_projT[128*128];
static __device__ __align__(16) float g_preT [64*64];
static __device__ __align__(16) float g_qkvT [64*192];
static __device__ __align__(16) float g_g1T  [64*32];
static __device__ __align__(16) float g_postT[64*64];
static __device__ __align__(16) float g_poutT[128*128];

static __device__ __align__(16) float g_lb  [(size_t)4*64*HW];   // local branch residual
static __device__ __align__(16) float g_gb  [(size_t)4*64*HW];   // global branch
static __device__ __align__(16) float g_xpre[(size_t)4*64*HW];   // lgce pre-conv output
static __device__ __align__(16) float g_qkv [(size_t)4*192*HW];  // qkv before dwconv
static __device__ __align__(16) float g_qkvd[(size_t)4*192*HW];  // qkv after dwconv

static __device__ double g_pooled[4*64];
static __device__ double g_gate_sum;
static __device__ double g_resp_sum[4*8];
static __device__ double g_gram[4*8*64];
static __device__ double g_qss[4*64];
static __device__ double g_kss[4*64];
static __device__ float  g_cw[4*64];
static __device__ float  g_kdyn;
static __device__ float  g_attnw[4*8*64];

__device__ __forceinline__ float sigm(float v){ return 1.0f/(1.0f + __expf(-v)); }

// ---- packed f32x2 helpers ----
typedef unsigned long long u64;
__device__ __forceinline__ u64 pk2(float lo, float hi){
  u64 r; asm("mov.b64 %0, {%1,%2};" : "=l"(r) : "f"(lo), "f"(hi)); return r;
}
__device__ __forceinline__ void fma2(u64 &d, u64 a, u64 b){
  asm("fma.rn.f32x2 %0, %1, %2, %0;" : "+l"(d) : "l"(a), "l"(b));
}
__device__ __forceinline__ float2 upk2(u64 v){
  float2 f; asm("mov.b64 {%0,%1}, %2;" : "=f"(f.x), "=f"(f.y) : "l"(v)); return f;
}

// Shared CBAM response path: MUST be identical in k_thr and k_final.
__device__ __forceinline__ void group_resp(const float* xv, const float* cw8,
                                           const float* sw8, float sbg, float* resp)
{
  float xc[8]; float dot = sbg;
  #pragma unroll
  for (int c=0;c<8;c++){ xc[c] = xv[c]*cw8[c]; dot = fmaf(xc[c], sw8[c], dot); }
  float sp = sigm(dot);
  #pragma unroll
  for (int c=0;c<8;c++) resp[c] = sigm(xc[c]*sp);
}

// ------------------------------- k_prep -------------------------------
__global__ void k_prep(const float* __restrict__ pw, const float* __restrict__ prew,
                       const float* __restrict__ qw, const float* __restrict__ g1,
                       const float* __restrict__ postw, const float* __restrict__ poutw)
{
  int t = blockIdx.x*256 + threadIdx.x;
  int nt = gridDim.x*256;
  for (int i=t; i<128*128; i+=nt){ int o=i>>7, c=i&127; g_projT[c*128+o]=pw[i]; g_poutT[c*128+o]=poutw[i]; }
  for (int i=t; i<64*64;  i+=nt){ int o=i>>6, c=i&63;  g_preT[c*64+o]=prew[i]; g_postT[c*64+o]=postw[i]; }
  for (int i=t; i<192*64; i+=nt){ int o=i/64, c=i%64;  g_qkvT[c*192+o]=qw[i]; }
  for (int i=t; i<32*64;  i+=nt){ int o=i>>6, c=i&63;  g_g1T[c*32+o]=g1[i]; }
  if (t < 256){ g_pooled[t]=0.0; g_qss[t]=0.0; g_kss[t]=0.0; }
  for (int i=t; i<2048; i+=nt) g_gram[i]=0.0;
  if (t < 32) g_resp_sum[t]=0.0;
  if (t == 0) g_gate_sum=0.0;
}

// ------------------------------- kf_A: input_proj + lgce-pre -------------------------------
// 128-px tile, K-chunked weights. smem (floats): ws 8192 | xs 128*132 | spool 512
#define FA_XS  8192
#define FA_SP  (8192 + 128*132)   // 25088
#define FA_TOT (25088 + 512)      // 25600 floats = 100 KB -> 2 CTA/SM

__global__ void __launch_bounds__(256,2) kf_A(const float* __restrict__ x,
                                              const float* __restrict__ pre_b)
{
  extern __shared__ float sm[];
  float* ws    = sm;
  float* xs    = sm + FA_XS;
  float* spool = sm + FA_SP;
  int tid = threadIdx.x;
  int b   = blockIdx.x >> 9;
  int pb  = (blockIdx.x & 511) << 7;
  int oi  = tid & 31;
  int pg  = tid >> 5;       // 0..7 (warp-constant)
  int px0 = pg << 4;

  const float* xb = x + (size_t)b*128*HW + pb;
  for (int i=tid; i<128*32; i+=256){
    int ch=i>>5, q=i&31;
    ((float4*)(xs + ch*132))[q] = __ldg((const float4*)(xb + (size_t)ch*HW) + q);
  }

  u64 acc[4][8];
  #pragma unroll
  for (int i=0;i<4;i++){
    #pragma unroll
    for (int j=0;j<8;j++) acc[i][j]=0ull;
  }
  #pragma unroll
  for (int c=0;c<2;c++){
    __syncthreads();   // prior chunk reads done (and xs load for c=0)
    for (int i=tid; i<64*32; i+=256) ((float4*)ws)[i] = ((const float4*)(g_projT + c*8192))[i];
    __syncthreads();
    for (int kk=0; kk<64; kk++){
      const ulonglong2* xr = (const ulonglong2*)(xs + (c*64+kk)*132 + px0);
      ulonglong2 x01 = xr[0], x23 = xr[1], x45 = xr[2], x67 = xr[3];
      u64 xv[8] = {x01.x,x01.y,x23.x,x23.y,x45.x,x45.y,x67.x,x67.y};
      const float* wrow = ws + kk*128;
      #pragma unroll
      for (int i=0;i<4;i++){
        float w = wrow[oi + 32*i];
        u64 wp = pk2(w,w);
        #pragma unroll
        for (int j=0;j<8;j++) fma2(acc[i][j], wp, xv[j]);
      }
    }
  }
  __syncthreads();
  // write proj result in place over xs (all reads done)
  #pragma unroll
  for (int i=0;i<4;i++){
    ulonglong2* dst = (ulonglong2*)(xs + (oi+32*i)*132 + px0);
    #pragma unroll
    for (int m=0;m<4;m++){ ulonglong2 v; v.x=acc[i][2*m]; v.y=acc[i][2*m+1]; dst[m]=v; }
  }
  __syncthreads();
  // store lb (rows 0..63) and gb (rows 64..127); load preT over ws
  {
    float* lbp = g_lb + (size_t)b*64*HW + pb;
    float* gbp = g_gb + (size_t)b*64*HW + pb;
    for (int i=tid; i<64*32; i+=256){
      int ch=i>>5, q=i&31;
      *((float4*)(lbp + (size_t)ch*HW) + q) = ((const float4*)(xs + ch*132))[q];
      *((float4*)(gbp + (size_t)ch*HW) + q) = ((const float4*)(xs + (64+ch)*132))[q];
    }
    for (int i=tid; i<64*16; i+=256) ((float4*)ws)[i] = ((const float4*)g_preT)[i];
  }
  __syncthreads();
  // lgce pre conv: 64 outs x 128 px, K=64 (reads rows 0..63, writes rows 64..127)
  {
    u64 a2[2][8];
    #pragma unroll
    for (int i=0;i<2;i++){
      #pragma unroll
      for (int j=0;j<8;j++) a2[i][j]=0ull;
    }
    for (int k=0; k<64; k++){
      const ulonglong2* xr = (const ulonglong2*)(xs + k*132 + px0);
      ulonglong2 x01 = xr[0], x23 = xr[1], x45 = xr[2], x67 = xr[3];
      u64 xv[8] = {x01.x,x01.y,x23.x,x23.y,x45.x,x45.y,x67.x,x67.y};
      const float* wrow = ws + k*64;
      #pragma unroll
      for (int i=0;i<2;i++){
        float w = wrow[oi + 32*i];
        u64 wp = pk2(w,w);
        #pragma unroll
        for (int j=0;j<8;j++) fma2(a2[i][j], wp, xv[j]);
      }
    }
    #pragma unroll
    for (int i=0;i<2;i++){
      int o = oi + 32*i;
      float bb = __ldg(pre_b + o);
      float psum = 0.f;
      float* dst = xs + (64+o)*132 + px0;
      #pragma unroll
      for (int j=0;j<8;j++){
        float2 v = upk2(a2[i][j]);
        v.x += bb; v.y += bb;
        psum += v.x + v.y;
        *((float2*)(dst + 2*j)) = v;
      }
      spool[o*8 + pg] = psum;
    }
  }
  __syncthreads();
  {
    float* xpp = g_xpre + (size_t)b*64*HW + pb;
    for (int i=tid; i<64*32; i+=256){
      int ch=i>>5, q=i&31;
      *((float4*)(xpp + (size_t)ch*HW) + q) = ((const float4*)(xs + (64+ch)*132))[q];
    }
    if (tid < 64){
      float s = 0.f;
      #pragma unroll
      for (int t2=0;t2<8;t2++) s += spool[tid*8 + t2];
      atomicAdd(&g_pooled[b*64 + tid], (double)s);
    }
  }
}

// ------------------------------- kf_B: qkv + gate (512 threads, 128-px tile) -------------------------------
#define FB_WQ  0
#define FB_WG  12288
#define FB_XG  14336
#define FB_HID (14336 + 64*132)            // 22784
#define FB_STG (22784 + 128*33)            // 27008
#define FB_TOT (27008 + 64*132)            // 35456 floats = 141.8 KB

__global__ void __launch_bounds__(512,1) kf_B(
    const float* __restrict__ gate_b1, const float* __restrict__ gate_w2,
    const float* __restrict__ gate_b2)
{
  extern __shared__ float sm[];
  float* wsQ = sm + FB_WQ;
  float* wsG = sm + FB_WG;
  float* xg  = sm + FB_XG;
  float* hid = sm + FB_HID;
  float* stg = sm + FB_STG;
  int tid = threadIdx.x;
  int b   = blockIdx.x >> 9;
  int pb  = (blockIdx.x & 511) << 7;
  int oi  = tid & 63;
  int pg  = tid >> 6;       // 0..7 (warp-constant)
  int px0 = pg << 4;

  for (int i=tid; i<64*48; i+=512) ((float4*)wsQ)[i] = ((const float4*)g_qkvT)[i];
  for (int i=tid; i<64*8;  i+=512) ((float4*)wsG)[i] = ((const float4*)g_g1T)[i];
  const float* gbp = g_gb + (size_t)b*64*HW + pb;
  for (int i=tid; i<64*32; i+=512){
    int ch=i>>5, q=i&31;
    ((float4*)(xg + ch*132))[q] = __ldg((const float4*)(gbp + (size_t)ch*HW) + q);
  }
  __syncthreads();

  // gate hidden: 32 x 128 px
  {
    int o0 = (tid & 3) << 3;
    int p  = tid >> 2;     // 0..127
    u64 acc[4];
    #pragma unroll
    for (int i=0;i<4;i++) acc[i]=0ull;
    #pragma unroll 4
    for (int k=0;k<64;k++){
      float xv = xg[k*132 + p];
      u64 xp = pk2(xv,xv);
      float4 w0 = *((const float4*)(wsG + k*32 + o0));
      float4 w1 = *((const float4*)(wsG + k*32 + o0) + 1);
      fma2(acc[0], pk2(w0.x,w0.y), xp);
      fma2(acc[1], pk2(w0.z,w0.w), xp);
      fma2(acc[2], pk2(w1.x,w1.y), xp);
      fma2(acc[3], pk2(w1.z,w1.w), xp);
    }
    #pragma unroll
    for (int i=0;i<4;i++){
      float2 v = upk2(acc[i]);
      hid[p*33 + o0 + 2*i]     = fmaxf(v.x + __ldg(gate_b1 + o0 + 2*i), 0.f);
      hid[p*33 + o0 + 2*i + 1] = fmaxf(v.y + __ldg(gate_b1 + o0 + 2*i + 1), 0.f);
    }
  }
  __syncthreads();
  if (tid < 128){
    float g = __ldg(gate_b2);
    #pragma unroll
    for (int h=0;h<32;h++) g = fmaf(hid[tid*33+h], __ldg(gate_w2+h), g);
    g = sigm(g);
    #pragma unroll
    for (int off=16; off; off>>=1) g += __shfl_down_sync(0xffffffffu, g, off);
    if ((tid&31)==0) atomicAdd(&g_gate_sum, (double)g);
  }

  // qkv: 192 outs x 128 px, K=64; o = oi + 64*i
  u64 acc[3][8];
  #pragma unroll
  for (int i=0;i<3;i++){
    #pragma unroll
    for (int j=0;j<8;j++) acc[i][j]=0ull;
  }
  for (int k=0; k<64; k++){
    const ulonglong2* xr = (const ulonglong2*)(xg + k*132 + px0);
    ulonglong2 x01 = xr[0], x23 = xr[1], x45 = xr[2], x67 = xr[3];
    u64 xv[8] = {x01.x,x01.y,x23.x,x23.y,x45.x,x45.y,x67.x,x67.y};
    const float* wrow = wsQ + k*192;
    #pragma unroll
    for (int i=0;i<3;i++){
      float w = wrow[oi + 64*i];
      u64 wp = pk2(w,w);
      #pragma unroll
      for (int j=0;j<8;j++) fma2(acc[i][j], wp, xv[j]);
    }
  }
  // 3 staging waves
  float* qp = g_qkv + (size_t)b*192*HW + pb;
  #pragma unroll
  for (int w=0; w<3; w++){
    __syncthreads();
    {
      ulonglong2* dst = (ulonglong2*)(stg + oi*132 + px0);
      #pragma unroll
      for (int m=0;m<4;m++){ ulonglong2 v; v.x=acc[w][2*m]; v.y=acc[w][2*m+1]; dst[m]=v; }
    }
    __syncthreads();
    for (int t=tid; t<64*32; t+=512){
      int ch=t>>5, q=t&31;
      *((float4*)(qp + (size_t)(w*64+ch)*HW) + q) = ((const float4*)(stg + ch*132))[q];
    }
  }
}

// ------------------------------- k_dw: depthwise 3x3 SAME, all 192 ch -------------------------------
__global__ void __launch_bounds__(256) k_dw(const float* __restrict__ dww)
{
  int bid = blockIdx.x;                 // 768 * 64
  int bc  = bid >> 6;                   // b*192 + ch
  int y   = ((bid & 63) << 2) + (threadIdx.x >> 6);
  int xq  = (threadIdx.x & 63) << 2;
  int ch  = bc % 192;
  float w[9];
  #pragma unroll
  for (int i=0;i<9;i++) w[i] = __ldg(dww + ch*9 + i);
  const float* img = g_qkv + (size_t)bc*HW;
  float v[3][6];
  #pragma unroll
  for (int r=0;r<3;r++){
    int yy = y - 1 + r;
    if ((unsigned)yy < 256u){
      float4 c4 = __ldg((const float4*)(img + yy*IMW + xq));
      v[r][1]=c4.x; v[r][2]=c4.y; v[r][3]=c4.z; v[r][4]=c4.w;
      v[r][0] = (xq > 0)   ? __ldg(img + yy*IMW + xq - 1) : 0.f;
      v[r][5] = (xq < 252) ? __ldg(img + yy*IMW + xq + 4) : 0.f;
    } else {
      #pragma unroll
      for (int j=0;j<6;j++) v[r][j]=0.f;
    }
  }
  float o[4];
  #pragma unroll
  for (int j=0;j<4;j++){
    float s=0.f;
    #pragma unroll
    for (int r=0;r<3;r++){
      s = fmaf(v[r][j],   w[r*3+0], s);
      s = fmaf(v[r][j+1], w[r*3+1], s);
      s = fmaf(v[r][j+2], w[r*3+2], s);
    }
    o[j]=s;
  }
  float4 ov = {o[0],o[1],o[2],o[3]};
  *((float4*)(g_qkvd + (size_t)bc*HW + y*IMW + xq)) = ov;
}

// ------------------------------- k_small -------------------------------
__global__ void k_small(const float* __restrict__ w1, const float* __restrict__ b1,
                        const float* __restrict__ w2, const float* __restrict__ b2)
{
  int t = threadIdx.x;
  if (t < 32){
    int b = t >> 3, g = t & 7;
    float pooled[8];
    #pragma unroll
    for (int c=0;c<8;c++) pooled[c] = (float)(g_pooled[b*64 + g*8 + c] * (1.0/65536.0));
    float h0 = b1[g*2+0], h1 = b1[g*2+1];
    #pragma unroll
    for (int c=0;c<8;c++){
      h0 = fmaf(pooled[c], w1[g*16 + 0*8 + c], h0);
      h1 = fmaf(pooled[c], w1[g*16 + 1*8 + c], h1);
    }
    h0 = fmaxf(h0, 0.f); h1 = fmaxf(h1, 0.f);
    #pragma unroll
    for (int c=0;c<8;c++){
      float v = b2[g*8+c];
      v = fmaf(h0, w2[g*16 + c*2 + 0], v);
      v = fmaf(h1, w2[g*16 + c*2 + 1], v);
      g_cw[b*64 + g*8 + c] = sigm(v);
    }
    if (t == 0){
      float mean = (float)(g_gate_sum * (1.0/262144.0));
      g_kdyn = fminf(fmaxf(floorf(8.f*mean), 1.f), 8.f);
    }
  }
}

// ------------------------------- k_thr -------------------------------
__global__ void __launch_bounds__(256) k_thr(const float* __restrict__ sw, const float* __restrict__ sb)
{
  __shared__ float cw_s[64], sw_s[64], sb_s[8];
  __shared__ float ssum[8];
  int tid = threadIdx.x;
  int b = blockIdx.x >> 6;
  int p = ((blockIdx.x & 63) << 10) + tid*4;
  if (tid < 64){ cw_s[tid] = g_cw[b*64 + tid]; sw_s[tid] = __ldg(sw + tid); }
  if (tid < 8){ sb_s[tid] = __ldg(sb + tid); ssum[tid] = 0.f; }
  __syncthreads();
  const float* xp = g_xpre + (size_t)b*64*HW + p;
  #pragma unroll
  for (int g=0; g<8; g++){
    float4 xv4[8];
    #pragma unroll
    for (int c=0;c<8;c++) xv4[c] = __ldg((const float4*)(xp + (size_t)(g*8+c)*HW));
    float s = 0.f;
    #pragma unroll
    for (int px=0; px<4; px++){
      float xv[8], resp[8];
      #pragma unroll
      for (int c=0;c<8;c++) xv[c] = ((const float*)&xv4[c])[px];
      group_resp(xv, cw_s + g*8, sw_s + g*8, sb_s[g], resp);
      #pragma unroll
      for (int c=0;c<8;c++) s += resp[c];
    }
    #pragma unroll
    for (int off=16; off; off>>=1) s += __shfl_down_sync(0xffffffffu, s, off);
    if ((tid&31)==0) atomicAdd(&ssum[g], s);
  }
  __syncthreads();
  if (tid < 8) atomicAdd(&g_resp_sum[b*8 + tid], (double)ssum[tid]);
}

// ------------------------------- k_gram: register-resident, float4 global loads -------------------------------
__global__ void __launch_bounds__(256) k_gram()
{
  __shared__ float wred[8*80];
  int tid = threadIdx.x;
  int b  = blockIdx.x >> 6;
  int h  = (blockIdx.x >> 3) & 7;
  int sl = blockIdx.x & 7;
  const float* qb = g_qkvd + (size_t)(b*192 + h*8)*HW;
  const float* kb = g_qkvd + (size_t)(b*192 + 64 + h*8)*HW;

  float gr[8][8], qs[8], ks[8];
  #pragma unroll
  for (int c=0;c<8;c++){
    qs[c]=0.f; ks[c]=0.f;
    #pragma unroll
    for (int d=0;d<8;d++) gr[c][d]=0.f;
  }
  for (int it=0; it<8; it++){
    int p = sl*8192 + it*1024 + tid*4;
    float4 q[8], k[8];
    #pragma unroll
    for (int c=0;c<8;c++){
      q[c]=__ldg((const float4*)(qb + (size_t)c*HW + p));
      k[c]=__ldg((const float4*)(kb + (size_t)c*HW + p));
    }
    #pragma unroll
    for (int c=0;c<8;c++){
      qs[c]=fmaf(q[c].x,q[c].x,qs[c]); qs[c]=fmaf(q[c].y,q[c].y,qs[c]);
      qs[c]=fmaf(q[c].z,q[c].z,qs[c]); qs[c]=fmaf(q[c].w,q[c].w,qs[c]);
      ks[c]=fmaf(k[c].x,k[c].x,ks[c]); ks[c]=fmaf(k[c].y,k[c].y,ks[c]);
      ks[c]=fmaf(k[c].z,k[c].z,ks[c]); ks[c]=fmaf(k[c].w,k[c].w,ks[c]);
      #pragma unroll
      for (int d=0;d<8;d++){
        gr[c][d]=fmaf(q[c].x,k[d].x,gr[c][d]);
        gr[c][d]=fmaf(q[c].y,k[d].y,gr[c][d]);
        gr[c][d]=fmaf(q[c].z,k[d].z,gr[c][d]);
        gr[c][d]=fmaf(q[c].w,k[d].w,gr[c][d]);
      }
    }
  }
  int lane = tid & 31, wd = tid >> 5;
  #pragma unroll
  for (int c=0;c<8;c++){
    #pragma unroll
    for (int d=0;d<8;d++){
      float v = gr[c][d];
      #pragma unroll
      for (int o=16;o;o>>=1) v += __shfl_down_sync(0xffffffffu, v, o);
      if (lane==0) wred[wd*80 + c*8 + d] = v;
    }
  }
  #pragma unroll
  for (int c=0;c<8;c++){
    float v = qs[c];
    #pragma unroll
    for (int o=16;o;o>>=1) v += __shfl_down_sync(0xffffffffu, v, o);
    if (lane==0) wred[wd*80 + 64 + c] = v;
    float u = ks[c];
    #pragma unroll
    for (int o=16;o;o>>=1) u += __shfl_down_sync(0xffffffffu, u, o);
    if (lane==0) wred[wd*80 + 72 + c] = u;
  }
  __syncthreads();
  if (tid < 80){
    float s = 0.f;
    #pragma unroll
    for (int ww=0; ww<8; ww++) s += wred[ww*80 + tid];
    if (tid < 64)      atomicAdd(&g_gram[(b*8+h)*64 + tid], (double)s);
    else if (tid < 72) atomicAdd(&g_qss[b*64 + h*8 + (tid-64)], (double)s);
    else               atomicAdd(&g_kss[b*64 + h*8 + (tid-72)], (double)s);
  }
}

// ------------------------------- k_attn -------------------------------
__global__ void k_attn(const float* __restrict__ temp, const float* __restrict__ scales)
{
  int t = threadIdx.x;
  if (t >= 32) return;
  int b = t >> 3, h = t & 7;
  float scl = scales[0] + scales[1] + scales[2] + scales[3];
  float T   = temp[h];
  float kd  = g_kdyn;
  float nq[8], nk[8];
  #pragma unroll
  for (int c=0;c<8;c++){
    nq[c] = fmaxf(sqrtf((float)g_qss[b*64 + h*8 + c]), 1e-12f);
    nk[c] = fmaxf(sqrtf((float)g_kss[b*64 + h*8 + c]), 1e-12f);
  }
  float a[8][8];
  #pragma unroll
  for (int c=0;c<8;c++){
    #pragma unroll
    for (int d=0;d<8;d++)
      a[c][d] = ((float)g_gram[(b*8+h)*64 + c*8 + d]) / (nq[c]*nk[d]) * T;
  }
  #pragma unroll
  for (int c=0;c<8;c++){
    bool keep[8];
    #pragma unroll
    for (int d=0;d<8;d++){
      int r = 0;
      #pragma unroll
      for (int e=0;e<8;e++)
        r += (a[c][e] > a[c][d]) || (a[c][e] == a[c][d] && e < d);
      keep[d] = ((float)r < kd);
    }
    float m = -1e30f;
    #pragma unroll
    for (int d=0;d<8;d++) if (keep[d]) m = fmaxf(m, a[c][d]);
    float pr[8]; float sum = 0.f;
    #pragma unroll
    for (int d=0;d<8;d++){ pr[d] = keep[d] ? __expf(a[c][d]-m) : 0.f; sum += pr[d]; }
    float inv = scl / sum;
    #pragma unroll
    for (int d=0;d<8;d++) g_attnw[((b*8+h)*8 + c)*8 + d] = pr[d]*inv;
  }
}

// ------------------------------- k_final -------------------------------
// 64-px tile. smem: wb 16384 (wpost first, wpout reloaded) | xs 64*68 | vb 64*68 | W 512 | cw 64 | thr 8
#define FN_XS  16384
#define FN_VB  (16384 + 64*68)          // 20736
#define FN_WS  (20736 + 64*68)          // 25088
#define FN_CW  (25088 + 512)            // 25600
#define FN_THR (25600 + 64)             // 25664
#define FN_TOT (25664 + 8)              // 25672 floats = 102.7 KB -> 2 CTA/SM

__global__ void __launch_bounds__(256,2) k_final(
    const float* __restrict__ sw, const float* __restrict__ sb,
    const float* __restrict__ post_b, float* __restrict__ out)
{
  extern __shared__ float sm[];
  float* wb    = sm;
  float* xs    = sm + FN_XS;
  float* vb    = sm + FN_VB;
  float* W_s   = sm + FN_WS;
  float* cw_s  = sm + FN_CW;
  float* thr_s = sm + FN_THR;

  int tid = threadIdx.x;
  int b   = blockIdx.x >> 10;
  int pb  = (blockIdx.x & 1023) << 6;
  int oi  = tid & 63;
  int qg  = tid >> 6;        // 0..3 (warp-constant)
  int px0 = qg << 4;

  for (int i=tid; i<1024; i+=256) ((float4*)wb)[i] = ((const float4*)g_postT)[i];
  for (int i=tid; i<512;  i+=256) W_s[i] = g_attnw[b*512 + i];
  if (tid < 64) cw_s[tid] = g_cw[b*64 + tid];
  if (tid < 8)  thr_s[tid] = (float)(g_resp_sum[b*8 + tid] * (1.0/524288.0));
  {
    const float* xp  = g_xpre + (size_t)b*64*HW + pb;
    const float* lbp = g_lb   + (size_t)b*64*HW + pb;
    for (int i=tid; i<64*16; i+=256){
      int ch=i>>4, q=i&15;
      ((float4*)(xs + ch*68))[q] = __ldg((const float4*)(xp  + (size_t)ch*HW) + q);
      ((float4*)(vb + ch*68))[q] = __ldg((const float4*)(lbp + (size_t)ch*HW) + q);
    }
  }
  __syncthreads();

  // mask in place (same group_resp as k_thr)
  {
    int p  = tid & 63;
    int g0 = (tid >> 6) << 1;
    #pragma unroll
    for (int gi=0; gi<2; gi++){
      int g = g0 + gi;
      float xv[8], resp[8], sw8[8];
      #pragma unroll
      for (int c=0;c<8;c++){ xv[c] = xs[(g*8+c)*68 + p]; sw8[c] = __ldg(sw + g*8 + c); }
      group_resp(xv, cw_s + g*8, sw8, __ldg(sb + g), resp);
      float thr = thr_s[g];
      #pragma unroll
      for (int c=0;c<8;c++){
        float m = resp[c] > thr ? 1.f : resp[c];
        xs[(g*8+c)*68 + p] = xv[c]*m;
      }
    }
  }
  __syncthreads();

  // post conv: 1 out x 16 px per thread, K=64; + bias + residual (vb = lb)
  float pres[16];
  {
    u64 pa[8];
    #pragma unroll
    for (int j=0;j<8;j++) pa[j]=0ull;
    for (int k=0; k<64; k++){
      const ulonglong2* xr = (const ulonglong2*)(xs + k*68 + px0);
      ulonglong2 x01 = xr[0], x23 = xr[1], x45 = xr[2], x67 = xr[3];
      u64 xv[8] = {x01.x,x01.y,x23.x,x23.y,x45.x,x45.y,x67.x,x67.y};
      float w = wb[k*64 + oi];
      u64 wp = pk2(w,w);
      #pragma unroll
      for (int j=0;j<8;j++) fma2(pa[j], wp, xv[j]);
    }
    float bb = __ldg(post_b + oi);
    const float* rr = vb + oi*68 + px0;
    #pragma unroll
    for (int j=0;j<8;j++){
      float2 v = upk2(pa[j]);
      pres[2*j]   = v.x + bb + rr[2*j];
      pres[2*j+1] = v.y + bb + rr[2*j+1];
    }
  }
  __syncthreads();
  {
    // write post result into xs row oi; overwrite vb with dwconv'd v tile
    float* dst = xs + oi*68 + px0;
    #pragma unroll
    for (int j=0;j<8;j++) *((float2*)(dst + 2*j)) = make_float2(pres[2*j], pres[2*j+1]);
    const float* vp = g_qkvd + (size_t)(b*192 + 128)*HW + pb;
    for (int i=tid; i<64*16; i+=256){
      int ch=i>>4, q=i&15;
      ((float4*)(vb + ch*68))[q] = __ldg((const float4*)(vp + (size_t)ch*HW) + q);
    }
  }
  __syncthreads();

  // attn mix: out oi (head oi>>3, ch oi&7), 16 px
  {
    int h = oi >> 3;
    u64 aa[8];
    #pragma unroll
    for (int j=0;j<8;j++) aa[j]=0ull;
    #pragma unroll
    for (int d=0;d<8;d++){
      float w = W_s[oi*8 + d];
      u64 wp = pk2(w,w);
      const ulonglong2* xr = (const ulonglong2*)(vb + (h*8+d)*68 + px0);
      ulonglong2 x01 = xr[0], x23 = xr[1], x45 = xr[2], x67 = xr[3];
      fma2(aa[0], wp, x01.x); fma2(aa[1], wp, x01.y);
      fma2(aa[2], wp, x23.x); fma2(aa[3], wp, x23.y);
      fma2(aa[4], wp, x45.x); fma2(aa[5], wp, x45.y);
      fma2(aa[6], wp, x67.x); fma2(aa[7], wp, x67.y);
    }
    __syncthreads();   // all vb reads done
    ulonglong2* dst = (ulonglong2*)(vb + oi*68 + px0);
    #pragma unroll
    for (int m=0;m<4;m++){ ulonglong2 v; v.x=aa[2*m]; v.y=aa[2*m+1]; dst[m]=v; }
    // reload wb with proj_out weights
    for (int i=tid; i<4096; i+=256) ((float4*)wb)[i] = ((const float4*)g_poutT)[i];
  }
  __syncthreads();

  // proj_out: 2 outs (oi, oi+64) x 16 px, K=128 (k<64 -> vb=attn, k>=64 -> xs=post)
  {
    u64 po[2][8];
    #pragma unroll
    for (int i=0;i<2;i++){
      #pragma unroll
      for (int j=0;j<8;j++) po[i][j]=0ull;
    }
    for (int k=0; k<64; k++){
      const ulonglong2* xr = (const ulonglong2*)(vb + k*68 + px0);
      ulonglong2 x01 = xr[0], x23 = xr[1], x45 = xr[2], x67 = xr[3];
      u64 xv[8] = {x01.x,x01.y,x23.x,x23.y,x45.x,x45.y,x67.x,x67.y};
      const float* wrow = wb + k*128;
      #pragma unroll
      for (int i=0;i<2;i++){
        float w = wrow[oi + 64*i];
        u64 wp = pk2(w,w);
        #pragma unroll
        for (int j=0;j<8;j++) fma2(po[i][j], wp, xv[j]);
      }
    }
    for (int k=0; k<64; k++){
      const ulonglong2* xr = (const ulonglong2*)(xs + k*68 + px0);
      ulonglong2 x01 = xr[0], x23 = xr[1], x45 = xr[2], x67 = xr[3];
      u64 xv[8] = {x01.x,x01.y,x23.x,x23.y,x45.x,x45.y,x67.x,x67.y};
      const float* wrow = wb + (64+k)*128;
      #pragma unroll
      for (int i=0;i<2;i++){
        float w = wrow[oi + 64*i];
        u64 wp = pk2(w,w);
        #pragma unroll
        for (int j=0;j<8;j++) fma2(po[i][j], wp, xv[j]);
      }
    }
    __syncthreads();   // all vb/xs reads done
    ulonglong2* d0 = (ulonglong2*)(vb + oi*68 + px0);
    ulonglong2* d1 = (ulonglong2*)(xs + oi*68 + px0);
    #pragma unroll
    for (int m=0;m<4;m++){
      ulonglong2 v0; v0.x=po[0][2*m]; v0.y=po[0][2*m+1]; d0[m]=v0;
      ulonglong2 v1; v1.x=po[1][2*m]; v1.y=po[1][2*m+1]; d1[m]=v1;
    }
  }
  __syncthreads();
  {
    float* op = out + (size_t)b*128*HW + pb;
    for (int i=tid; i<64*16; i+=256){
      int ch=i>>4, q=i&15;
      *((float4*)(op + (size_t)ch*HW) + q)      = ((const float4*)(vb + ch*68))[q];
      *((float4*)(op + (size_t)(64+ch)*HW) + q) = ((const float4*)(xs + ch*68))[q];
    }
  }
}

// ------------------------------- launch -------------------------------
extern "C" void kernel_launch(void* const* d_in, const int* in_sizes, int n_in,
                              void* d_out, int out_size)
{
  const float* x      = (const float*)d_in[0];
  const float* projw  = (const float*)d_in[1];
  const float* prew   = (const float*)d_in[2];
  const float* preb   = (const float*)d_in[3];
  const float* w1     = (const float*)d_in[4];
  const float* b1     = (const float*)d_in[5];
  const float* w2     = (const float*)d_in[6];
  const float* b2     = (const float*)d_in[7];
  const float* sw     = (const float*)d_in[8];
  const float* sb     = (const float*)d_in[9];
  const float* postw  = (const float*)d_in[10];
  const float* postb  = (const float*)d_in[11];
  const float* qkvw   = (const float*)d_in[12];
  const float* dww    = (const float*)d_in[13];
  const float* gw1    = (const float*)d_in[14];
  const float* gb1    = (const float*)d_in[15];
  const float* gw2    = (const float*)d_in[16];
  const float* gb2    = (const float*)d_in[17];
  const float* temp   = (const float*)d_in[18];
  const float* scales = (const float*)d_in[19];
  const float* poutw  = (const float*)d_in[20];
  float* out = (float*)d_out;

  cudaFuncSetAttribute(kf_A,   cudaFuncAttributeMaxDynamicSharedMemorySize, FA_TOT*4);
  cudaFuncSetAttribute(kf_B,   cudaFuncAttributeMaxDynamicSharedMemorySize, FB_TOT*4);
  cudaFuncSetAttribute(k_final, cudaFuncAttributeMaxDynamicSharedMemorySize, FN_TOT*4);

  k_prep <<<64, 256>>>(projw, prew, qkvw, gw1, postw, poutw);
  kf_A  <<<2048, 256, FA_TOT*4>>>(x, preb);
  kf_B  <<<2048, 512, FB_TOT*4>>>(gb1, gw2, gb2);
  k_dw  <<<768*64, 256>>>(dww);
  k_small<<<1, 32>>>(w1, b1, w2, b2);
  k_thr <<<256, 256>>>(sw, sb);
  k_gram<<<256, 256>>>();
  k_attn<<<1, 32>>>(temp, scales);
  k_final<<<4096, 256, FN_TOT*4>>>(sw, sb, postb, out);
}

// round 7
// speedup vs baseline: 2.6266x; 1.0141x over previous
#include <cuda_runtime.h>

#define HW 65536
#define IMW 256

// ------------------------- device scratch (no allocations) -------------------------
static __device__ __align__(16) float g_projT[128*128];
static __device__ __align__(16) float g_preT [64*64];
static __device__ __align__(16) float g_qkvT [3*64*64];   // chunk-major: [cc][k][64]
static __device__ __align__(16) float g_g1T  [64*32];
static __device__ __align__(16) float g_postT[64*64];
static __device__ __align__(16) float g_poutT[128*128];

static __device__ __align__(16) float g_lb  [(size_t)4*64*HW];   // local branch residual
static __device__ __align__(16) float g_xpre[(size_t)4*64*HW];   // lgce pre-conv output
static __device__ __align__(16) float g_qkv [(size_t)4*192*HW];  // qkv (pre-dwconv)
static __device__ __align__(16) float g_vd  [(size_t)4*64*HW];   // dwconv'd v

static __device__ double g_pooled[4*64];
static __device__ double g_gate_sum;
static __device__ double g_resp_sum[4*8];
static __device__ double g_gram[4*8*64];
static __device__ double g_qss[4*64];
static __device__ double g_kss[4*64];
static __device__ float  g_cw[4*64];
static __device__ float  g_kdyn;
static __device__ float  g_attnw[4*8*64];

__device__ __forceinline__ float sigm(float v){ return 1.0f/(1.0f + __expf(-v)); }

// ---- packed f32x2 helpers ----
typedef unsigned long long u64;
__device__ __forceinline__ u64 pk2(float lo, float hi){
  u64 r; asm("mov.b64 %0, {%1,%2};" : "=l"(r) : "f"(lo), "f"(hi)); return r;
}
__device__ __forceinline__ void fma2(u64 &d, u64 a, u64 b){
  asm("fma.rn.f32x2 %0, %1, %2, %0;" : "+l"(d) : "l"(a), "l"(b));
}
__device__ __forceinline__ float2 upk2(u64 v){
  float2 f; asm("mov.b64 {%0,%1}, %2;" : "=f"(f.x), "=f"(f.y) : "l"(v)); return f;
}

// Shared CBAM response path: MUST be identical in k_thr and k_final.
__device__ __forceinline__ void group_resp(const float* xv, const float* cw8,
                                           const float* sw8, float sbg, float* resp)
{
  float xc[8]; float dot = sbg;
  #pragma unroll
  for (int c=0;c<8;c++){ xc[c] = xv[c]*cw8[c]; dot = fmaf(xc[c], sw8[c], dot); }
  float sp = sigm(dot);
  #pragma unroll
  for (int c=0;c<8;c++) resp[c] = sigm(xc[c]*sp);
}

// ------------------------------- k_prep -------------------------------
__global__ void k_prep(const float* __restrict__ pw, const float* __restrict__ prew,
                       const float* __restrict__ qw, const float* __restrict__ g1,
                       const float* __restrict__ postw, const float* __restrict__ poutw)
{
  int t = blockIdx.x*256 + threadIdx.x;
  int nt = gridDim.x*256;
  for (int i=t; i<128*128; i+=nt){ int o=i>>7, c=i&127; g_projT[c*128+o]=pw[i]; g_poutT[c*128+o]=poutw[i]; }
  for (int i=t; i<64*64;  i+=nt){ int o=i>>6, c=i&63;  g_preT[c*64+o]=prew[i]; g_postT[c*64+o]=postw[i]; }
  for (int i=t; i<192*64; i+=nt){ int o=i/64, c=i%64;  g_qkvT[(o>>6)*4096 + c*64 + (o&63)] = qw[i]; }
  for (int i=t; i<32*64;  i+=nt){ int o=i>>6, c=i&63;  g_g1T[c*32+o]=g1[i]; }
  if (t < 256){ g_pooled[t]=0.0; g_qss[t]=0.0; g_kss[t]=0.0; }
  for (int i=t; i<2048; i+=nt) g_gram[i]=0.0;
  if (t < 32) g_resp_sum[t]=0.0;
  if (t == 0) g_gate_sum=0.0;
}

// ------------------------------- k_front: proj + pre + gate + qkv -------------------------------
// smem (floats): ws 8192 | xs 128*132 | spool 512  (gate g1T+hid overlay ws)
#define FR_XS   8192
#define FR_SP   (8192 + 128*132)   // 25088
#define FR_TOT  (25088 + 512)      // 25600 floats = 100 KB -> 2 CTA/SM

__global__ void __launch_bounds__(256,2) k_front(
    const float* __restrict__ x, const float* __restrict__ pre_b,
    const float* __restrict__ gate_b1, const float* __restrict__ gate_w2,
    const float* __restrict__ gate_b2)
{
  extern __shared__ float sm[];
  float* ws    = sm;
  float* xs    = sm + FR_XS;
  float* spool = sm + FR_SP;
  int tid = threadIdx.x;
  int b   = blockIdx.x >> 9;
  int pb  = (blockIdx.x & 511) << 7;
  int oi  = tid & 31;
  int pg  = tid >> 5;       // 0..7 (warp-constant)
  int px0 = pg << 4;

  // load x tile
  const float* xb = x + (size_t)b*128*HW + pb;
  for (int i=tid; i<128*32; i+=256){
    int ch=i>>5, q=i&31;
    ((float4*)(xs + ch*132))[q] = __ldg((const float4*)(xb + (size_t)ch*HW) + q);
  }

  // ---- input_proj, 2 K-chunks ----
  u64 acc[4][8];
  #pragma unroll
  for (int i=0;i<4;i++){
    #pragma unroll
    for (int j=0;j<8;j++) acc[i][j]=0ull;
  }
  #pragma unroll
  for (int c=0;c<2;c++){
    __syncthreads();
    for (int i=tid; i<64*32; i+=256) ((float4*)ws)[i] = ((const float4*)(g_projT + c*8192))[i];
    __syncthreads();
    for (int kk=0; kk<64; kk++){
      const ulonglong2* xr = (const ulonglong2*)(xs + (c*64+kk)*132 + px0);
      ulonglong2 x01 = xr[0], x23 = xr[1], x45 = xr[2], x67 = xr[3];
      u64 xv[8] = {x01.x,x01.y,x23.x,x23.y,x45.x,x45.y,x67.x,x67.y};
      const float* wrow = ws + kk*128;
      #pragma unroll
      for (int i=0;i<4;i++){
        float w = wrow[oi + 32*i];
        u64 wp = pk2(w,w);
        #pragma unroll
        for (int j=0;j<8;j++) fma2(acc[i][j], wp, xv[j]);
      }
    }
  }
  __syncthreads();   // all xs reads done
  #pragma unroll
  for (int i=0;i<4;i++){
    ulonglong2* dst = (ulonglong2*)(xs + (oi+32*i)*132 + px0);
    #pragma unroll
    for (int m=0;m<4;m++){ ulonglong2 v; v.x=acc[i][2*m]; v.y=acc[i][2*m+1]; dst[m]=v; }
  }
  __syncthreads();

  // ---- store lb; load preT ----
  {
    float* lbp = g_lb + (size_t)b*64*HW + pb;
    for (int i=tid; i<64*32; i+=256){
      int ch=i>>5, q=i&31;
      *((float4*)(lbp + (size_t)ch*HW) + q) = ((const float4*)(xs + ch*132))[q];
    }
    for (int i=tid; i<64*16; i+=256) ((float4*)ws)[i] = ((const float4*)g_preT)[i];
  }
  __syncthreads();

  // ---- lgce pre conv (reads rows 0..63, writes rows 0..63 after reads) ----
  {
    u64 a2[2][8];
    #pragma unroll
    for (int i=0;i<2;i++){
      #pragma unroll
      for (int j=0;j<8;j++) a2[i][j]=0ull;
    }
    for (int k=0; k<64; k++){
      const ulonglong2* xr = (const ulonglong2*)(xs + k*132 + px0);
      ulonglong2 x01 = xr[0], x23 = xr[1], x45 = xr[2], x67 = xr[3];
      u64 xv[8] = {x01.x,x01.y,x23.x,x23.y,x45.x,x45.y,x67.x,x67.y};
      const float* wrow = ws + k*64;
      #pragma unroll
      for (int i=0;i<2;i++){
        float w = wrow[oi + 32*i];
        u64 wp = pk2(w,w);
        #pragma unroll
        for (int j=0;j<8;j++) fma2(a2[i][j], wp, xv[j]);
      }
    }
    __syncthreads();   // all reads of rows 0..63 done
    #pragma unroll
    for (int i=0;i<2;i++){
      int o = oi + 32*i;
      float bb = __ldg(pre_b + o);
      float psum = 0.f;
      float* dst = xs + o*132 + px0;
      #pragma unroll
      for (int j=0;j<8;j++){
        float2 v = upk2(a2[i][j]);
        v.x += bb; v.y += bb;
        psum += v.x + v.y;
        *((float2*)(dst + 2*j)) = v;
      }
      spool[o*8 + pg] = psum;
    }
  }
  __syncthreads();

  // ---- store xpre + pooled; load g1T into ws[0..2047] ----
  {
    float* xpp = g_xpre + (size_t)b*64*HW + pb;
    for (int i=tid; i<64*32; i+=256){
      int ch=i>>5, q=i&31;
      *((float4*)(xpp + (size_t)ch*HW) + q) = ((const float4*)(xs + ch*132))[q];
    }
    if (tid < 64){
      float s = 0.f;
      #pragma unroll
      for (int t2=0;t2<8;t2++) s += spool[tid*8 + t2];
      atomicAdd(&g_pooled[b*64 + tid], (double)s);
    }
    for (int i=tid; i<64*8; i+=256) ((float4*)ws)[i] = ((const float4*)g_g1T)[i];
  }
  __syncthreads();

  // ---- gate hidden: px = tid&127, out-half = tid>>7 (16 outs) ----
  {
    float* hid = ws + 2048;   // 128*33
    int px = tid & 127;
    int o0 = (tid >> 7) << 4;
    u64 ga[8];
    #pragma unroll
    for (int i=0;i<8;i++) ga[i]=0ull;
    #pragma unroll 4
    for (int k=0;k<64;k++){
      float xv = xs[(64+k)*132 + px];
      u64 xp = pk2(xv,xv);
      const float4* wr = (const float4*)(ws + k*32 + o0);
      float4 w0 = wr[0], w1 = wr[1], w2v = wr[2], w3 = wr[3];
      fma2(ga[0], pk2(w0.x,w0.y), xp);
      fma2(ga[1], pk2(w0.z,w0.w), xp);
      fma2(ga[2], pk2(w1.x,w1.y), xp);
      fma2(ga[3], pk2(w1.z,w1.w), xp);
      fma2(ga[4], pk2(w2v.x,w2v.y), xp);
      fma2(ga[5], pk2(w2v.z,w2v.w), xp);
      fma2(ga[6], pk2(w3.x,w3.y), xp);
      fma2(ga[7], pk2(w3.z,w3.w), xp);
    }
    #pragma unroll
    for (int i=0;i<8;i++){
      float2 v = upk2(ga[i]);
      hid[px*33 + o0 + 2*i]     = fmaxf(v.x + __ldg(gate_b1 + o0 + 2*i), 0.f);
      hid[px*33 + o0 + 2*i + 1] = fmaxf(v.y + __ldg(gate_b1 + o0 + 2*i + 1), 0.f);
    }
  }
  __syncthreads();
  if (tid < 128){
    const float* hid = ws + 2048;
    float g = __ldg(gate_b2);
    #pragma unroll
    for (int h=0;h<32;h++) g = fmaf(hid[tid*33+h], __ldg(gate_w2+h), g);
    g = sigm(g);
    #pragma unroll
    for (int off=16; off; off>>=1) g += __shfl_down_sync(0xffffffffu, g, off);
    if ((tid&31)==0) atomicAdd(&g_gate_sum, (double)g);
  }

  // ---- qkv: 3 out-chunks of 64, staging in rows 0..63 ----
  float* qp = g_qkv + (size_t)b*192*HW + pb;
  for (int cc=0; cc<3; cc++){
    __syncthreads();   // hid reads / prior stage-store reads done
    for (int i=tid; i<64*16; i+=256) ((float4*)ws)[i] = ((const float4*)(g_qkvT + cc*4096))[i];
    __syncthreads();
    u64 a2[2][8];
    #pragma unroll
    for (int i=0;i<2;i++){
      #pragma unroll
      for (int j=0;j<8;j++) a2[i][j]=0ull;
    }
    for (int k=0; k<64; k++){
      const ulonglong2* xr = (const ulonglong2*)(xs + (64+k)*132 + px0);
      ulonglong2 x01 = xr[0], x23 = xr[1], x45 = xr[2], x67 = xr[3];
      u64 xv[8] = {x01.x,x01.y,x23.x,x23.y,x45.x,x45.y,x67.x,x67.y};
      const float* wrow = ws + k*64;
      #pragma unroll
      for (int i=0;i<2;i++){
        float w = wrow[oi + 32*i];
        u64 wp = pk2(w,w);
        #pragma unroll
        for (int j=0;j<8;j++) fma2(a2[i][j], wp, xv[j]);
      }
    }
    // stage into rows 0..63 (disjoint from compute reads; prior readers synced)
    #pragma unroll
    for (int i=0;i<2;i++){
      ulonglong2* dst = (ulonglong2*)(xs + (oi+32*i)*132 + px0);
      #pragma unroll
      for (int m=0;m<4;m++){ ulonglong2 v; v.x=a2[i][2*m]; v.y=a2[i][2*m+1]; dst[m]=v; }
    }
    __syncthreads();
    for (int t=tid; t<64*32; t+=256){
      int ch=t>>5, q=t&31;
      *((float4*)(qp + (size_t)(cc*64+ch)*HW) + q) = ((const float4*)(xs + ch*132))[q];
    }
  }
}

// ------------------------------- k_dw: depthwise 3x3 SAME, V ONLY -------------------------------
__global__ void __launch_bounds__(256) k_dw(const float* __restrict__ dww)
{
  int bid = blockIdx.x;                 // 256 * 64
  int bcv = bid >> 6;                   // b*64 + cv
  int bb  = bcv >> 6, cv = bcv & 63;
  int ch  = 128 + cv;
  int y   = ((bid & 63) << 2) + (threadIdx.x >> 6);
  int xq  = (threadIdx.x & 63) << 2;
  float w[9];
  #pragma unroll
  for (int i=0;i<9;i++) w[i] = __ldg(dww + ch*9 + i);
  const float* img = g_qkv + (size_t)(bb*192 + ch)*HW;
  float v[3][6];
  #pragma unroll
  for (int r=0;r<3;r++){
    int yy = y - 1 + r;
    if ((unsigned)yy < 256u){
      float4 c4 = __ldg((const float4*)(img + yy*IMW + xq));
      v[r][1]=c4.x; v[r][2]=c4.y; v[r][3]=c4.z; v[r][4]=c4.w;
      v[r][0] = (xq > 0)   ? __ldg(img + yy*IMW + xq - 1) : 0.f;
      v[r][5] = (xq < 252) ? __ldg(img + yy*IMW + xq + 4) : 0.f;
    } else {
      #pragma unroll
      for (int j=0;j<6;j++) v[r][j]=0.f;
    }
  }
  float o[4];
  #pragma unroll
  for (int j=0;j<4;j++){
    float s=0.f;
    #pragma unroll
    for (int r=0;r<3;r++){
      s = fmaf(v[r][j],   w[r*3+0], s);
      s = fmaf(v[r][j+1], w[r*3+1], s);
      s = fmaf(v[r][j+2], w[r*3+2], s);
    }
    o[j]=s;
  }
  float4 ov = {o[0],o[1],o[2],o[3]};
  *((float4*)(g_vd + (size_t)(bb*64 + cv)*HW + y*IMW + xq)) = ov;
}

// ------------------------------- k_small -------------------------------
__global__ void k_small(const float* __restrict__ w1, const float* __restrict__ b1,
                        const float* __restrict__ w2, const float* __restrict__ b2)
{
  int t = threadIdx.x;
  if (t < 32){
    int b = t >> 3, g = t & 7;
    float pooled[8];
    #pragma unroll
    for (int c=0;c<8;c++) pooled[c] = (float)(g_pooled[b*64 + g*8 + c] * (1.0/65536.0));
    float h0 = b1[g*2+0], h1 = b1[g*2+1];
    #pragma unroll
    for (int c=0;c<8;c++){
      h0 = fmaf(pooled[c], w1[g*16 + 0*8 + c], h0);
      h1 = fmaf(pooled[c], w1[g*16 + 1*8 + c], h1);
    }
    h0 = fmaxf(h0, 0.f); h1 = fmaxf(h1, 0.f);
    #pragma unroll
    for (int c=0;c<8;c++){
      float v = b2[g*8+c];
      v = fmaf(h0, w2[g*16 + c*2 + 0], v);
      v = fmaf(h1, w2[g*16 + c*2 + 1], v);
      g_cw[b*64 + g*8 + c] = sigm(v);
    }
    if (t == 0){
      float mean = (float)(g_gate_sum * (1.0/262144.0));
      g_kdyn = fminf(fmaxf(floorf(8.f*mean), 1.f), 8.f);
    }
  }
}

// ------------------------------- k_thr -------------------------------
__global__ void __launch_bounds__(256) k_thr(const float* __restrict__ sw, const float* __restrict__ sb)
{
  __shared__ float cw_s[64], sw_s[64], sb_s[8];
  __shared__ float ssum[8];
  int tid = threadIdx.x;
  int b = blockIdx.x >> 6;
  int p = ((blockIdx.x & 63) << 10) + tid*4;
  if (tid < 64){ cw_s[tid] = g_cw[b*64 + tid]; sw_s[tid] = __ldg(sw + tid); }
  if (tid < 8){ sb_s[tid] = __ldg(sb + tid); ssum[tid] = 0.f; }
  __syncthreads();
  const float* xp = g_xpre + (size_t)b*64*HW + p;
  #pragma unroll
  for (int g=0; g<8; g++){
    float4 xv4[8];
    #pragma unroll
    for (int c=0;c<8;c++) xv4[c] = __ldg((const float4*)(xp + (size_t)(g*8+c)*HW));
    float s = 0.f;
    #pragma unroll
    for (int px=0; px<4; px++){
      float xv[8], resp[8];
      #pragma unroll
      for (int c=0;c<8;c++) xv[c] = ((const float*)&xv4[c])[px];
      group_resp(xv, cw_s + g*8, sw_s + g*8, sb_s[g], resp);
      #pragma unroll
      for (int c=0;c<8;c++) s += resp[c];
    }
    #pragma unroll
    for (int off=16; off; off>>=1) s += __shfl_down_sync(0xffffffffu, s, off);
    if ((tid&31)==0) atomicAdd(&ssum[g], s);
  }
  __syncthreads();
  if (tid < 8) atomicAdd(&g_resp_sum[b*8 + tid], (double)ssum[tid]);
}

// ------------------------------- k_gram: fused dwconv(q,k) + Gram -------------------------------
// grid = 4b * 8h * 32 row-strips (8 rows each). 256 threads = 256 columns.
// smem: sbuf 16ch x 3rows x 264 | wdw 160 | wred 640
#define GM_WDW  (16*792)            // 12672
#define GM_WRED (12672 + 160)       // 12832
#define GM_TOT  (12832 + 640)       // 13472 floats = 53.9 KB

__global__ void __launch_bounds__(256) k_gram(const float* __restrict__ dww)
{
  extern __shared__ float sm[];
  float* sbuf = sm;
  float* wdw  = sm + GM_WDW;
  float* wred = sm + GM_WRED;
  int tid = threadIdx.x;
  int bh    = blockIdx.x >> 5;
  int strip = blockIdx.x & 31;
  int b = bh >> 3, h = bh & 7;
  int r0 = strip << 3;

  if (tid < 144){
    int c = tid/9, j = tid%9;
    int ch = (c<8) ? (h*8+c) : (64 + h*8 + (c-8));
    wdw[tid] = __ldg(dww + ch*9 + j);
  }

  // row loader: global row ry -> slot (ry mod 3); zero-pads edge cells
  auto load_row = [&](int ry){
    int s = ((ry % 3) + 3) % 3;
    for (int i=tid; i<1024; i+=256){
      int c = i>>6, q = i&63;
      float4 v = {0.f,0.f,0.f,0.f};
      if ((unsigned)ry < 256u){
        int ch = (c<8) ? (h*8+c) : (64 + h*8 + (c-8));
        v = __ldg((const float4*)(g_qkv + (size_t)(b*192+ch)*HW + ry*IMW) + q);
      }
      *((float4*)(sbuf + c*792 + s*264 + 4 + 4*q)) = v;
    }
    if (tid < 32){
      int c = tid>>1, side = tid&1;
      sbuf[c*792 + s*264 + (side ? 260 : 3)] = 0.f;
    }
  };

  float gr[8][8], qs[8], ks[8];
  #pragma unroll
  for (int c=0;c<8;c++){
    qs[c]=0.f; ks[c]=0.f;
    #pragma unroll
    for (int d=0;d<8;d++) gr[c][d]=0.f;
  }

  load_row(r0-1);
  load_row(r0);
  int col = tid;
  for (int y=r0; y<r0+8; y++){
    load_row(y+1);
    __syncthreads();
    int s0 = ((y-1)%3 + 3)%3, s1 = y%3, s2 = (y+1)%3;
    int srow[3] = {s0, s1, s2};
    float q[8], k[8];
    #pragma unroll
    for (int c=0;c<8;c++){
      float aq = 0.f, ak = 0.f;
      #pragma unroll
      for (int r=0;r<3;r++){
        const float* pq = sbuf + c*792     + srow[r]*264 + 3 + col;
        const float* pk = sbuf + (8+c)*792 + srow[r]*264 + 3 + col;
        const float* wq = wdw + c*9 + r*3;
        const float* wk = wdw + 72 + c*9 + r*3;
        aq = fmaf(pq[0], wq[0], aq); aq = fmaf(pq[1], wq[1], aq); aq = fmaf(pq[2], wq[2], aq);
        ak = fmaf(pk[0], wk[0], ak); ak = fmaf(pk[1], wk[1], ak); ak = fmaf(pk[2], wk[2], ak);
      }
      q[c]=aq; k[c]=ak;
    }
    #pragma unroll
    for (int c=0;c<8;c++){
      qs[c]=fmaf(q[c],q[c],qs[c]); ks[c]=fmaf(k[c],k[c],ks[c]);
      #pragma unroll
      for (int d=0;d<8;d++) gr[c][d]=fmaf(q[c],k[d],gr[c][d]);
    }
    __syncthreads();   // reads of slot s0 done before next load overwrites it
  }

  // shuffle reduce -> smem -> 80 global fp64 atomics per block
  int lane = tid & 31, wd = tid >> 5;
  #pragma unroll
  for (int c=0;c<8;c++){
    #pragma unroll
    for (int d=0;d<8;d++){
      float v = gr[c][d];
      #pragma unroll
      for (int o=16;o;o>>=1) v += __shfl_down_sync(0xffffffffu, v, o);
      if (lane==0) wred[wd*80 + c*8 + d] = v;
    }
  }
  #pragma unroll
  for (int c=0;c<8;c++){
    float v = qs[c];
    #pragma unroll
    for (int o=16;o;o>>=1) v += __shfl_down_sync(0xffffffffu, v, o);
    if (lane==0) wred[wd*80 + 64 + c] = v;
    float u = ks[c];
    #pragma unroll
    for (int o=16;o;o>>=1) u += __shfl_down_sync(0xffffffffu, u, o);
    if (lane==0) wred[wd*80 + 72 + c] = u;
  }
  __syncthreads();
  if (tid < 80){
    float s = 0.f;
    #pragma unroll
    for (int ww=0; ww<8; ww++) s += wred[ww*80 + tid];
    if (tid < 64)      atomicAdd(&g_gram[(b*8+h)*64 + tid], (double)s);
    else if (tid < 72) atomicAdd(&g_qss[b*64 + h*8 + (tid-64)], (double)s);
    else               atomicAdd(&g_kss[b*64 + h*8 + (tid-72)], (double)s);
  }
}

// ------------------------------- k_attn -------------------------------
__global__ void k_attn(const float* __restrict__ temp, const float* __restrict__ scales)
{
  int t = threadIdx.x;
  if (t >= 32) return;
  int b = t >> 3, h = t & 7;
  float scl = scales[0] + scales[1] + scales[2] + scales[3];
  float T   = temp[h];
  float kd  = g_kdyn;
  float nq[8], nk[8];
  #pragma unroll
  for (int c=0;c<8;c++){
    nq[c] = fmaxf(sqrtf((float)g_qss[b*64 + h*8 + c]), 1e-12f);
    nk[c] = fmaxf(sqrtf((float)g_kss[b*64 + h*8 + c]), 1e-12f);
  }
  float a[8][8];
  #pragma unroll
  for (int c=0;c<8;c++){
    #pragma unroll
    for (int d=0;d<8;d++)
      a[c][d] = ((float)g_gram[(b*8+h)*64 + c*8 + d]) / (nq[c]*nk[d]) * T;
  }
  #pragma unroll
  for (int c=0;c<8;c++){
    bool keep[8];
    #pragma unroll
    for (int d=0;d<8;d++){
      int r = 0;
      #pragma unroll
      for (int e=0;e<8;e++)
        r += (a[c][e] > a[c][d]) || (a[c][e] == a[c][d] && e < d);
      keep[d] = ((float)r < kd);
    }
    float m = -1e30f;
    #pragma unroll
    for (int d=0;d<8;d++) if (keep[d]) m = fmaxf(m, a[c][d]);
    float pr[8]; float sum = 0.f;
    #pragma unroll
    for (int d=0;d<8;d++){ pr[d] = keep[d] ? __expf(a[c][d]-m) : 0.f; sum += pr[d]; }
    float inv = scl / sum;
    #pragma unroll
    for (int d=0;d<8;d++) g_attnw[((b*8+h)*8 + c)*8 + d] = pr[d]*inv;
  }
}

// ------------------------------- k_final: 128-px tiles, 512 threads -------------------------------
#define FN_XS  16384
#define FN_VB  (16384 + 64*132)          // 24832
#define FN_WS  (24832 + 64*132)          // 33280
#define FN_CW  (33280 + 512)             // 33792
#define FN_THR (33792 + 64)              // 33856
#define FN_TOT (33856 + 8)               // 33864 floats = 135.5 KB -> 1 CTA (16 warps)

__global__ void __launch_bounds__(512,1) k_final(
    const float* __restrict__ sw, const float* __restrict__ sb,
    const float* __restrict__ post_b, float* __restrict__ out)
{
  extern __shared__ float sm[];
  float* wb    = sm;
  float* xs    = sm + FN_XS;
  float* vb    = sm + FN_VB;
  float* W_s   = sm + FN_WS;
  float* cw_s  = sm + FN_CW;
  float* thr_s = sm + FN_THR;

  int tid = threadIdx.x;
  int b   = blockIdx.x >> 9;
  int pb  = (blockIdx.x & 511) << 7;
  int oi  = tid & 63;
  int qg  = tid >> 6;        // 0..7 (warp-pair constant)
  int px0 = qg << 4;

  for (int i=tid; i<1024; i+=512) ((float4*)wb)[i] = ((const float4*)g_postT)[i];
  for (int i=tid; i<512;  i+=512) W_s[i] = g_attnw[b*512 + i];
  if (tid < 64) cw_s[tid] = g_cw[b*64 + tid];
  if (tid < 8)  thr_s[tid] = (float)(g_resp_sum[b*8 + tid] * (1.0/524288.0));
  {
    const float* xp  = g_xpre + (size_t)b*64*HW + pb;
    const float* lbp = g_lb   + (size_t)b*64*HW + pb;
    for (int i=tid; i<64*32; i+=512){
      int ch=i>>5, q=i&31;
      ((float4*)(xs + ch*132))[q] = __ldg((const float4*)(xp  + (size_t)ch*HW) + q);
      ((float4*)(vb + ch*132))[q] = __ldg((const float4*)(lbp + (size_t)ch*HW) + q);
    }
  }
  __syncthreads();

  // mask in place (same group_resp as k_thr): 128 px x 8 groups / 512 threads
  {
    int p  = tid & 127;
    int g0 = (tid >> 7) << 1;
    #pragma unroll
    for (int gi=0; gi<2; gi++){
      int g = g0 + gi;
      float xv[8], resp[8], sw8[8];
      #pragma unroll
      for (int c=0;c<8;c++){ xv[c] = xs[(g*8+c)*132 + p]; sw8[c] = __ldg(sw + g*8 + c); }
      group_resp(xv, cw_s + g*8, sw8, __ldg(sb + g), resp);
      float thr = thr_s[g];
      #pragma unroll
      for (int c=0;c<8;c++){
        float m = resp[c] > thr ? 1.f : resp[c];
        xs[(g*8+c)*132 + p] = xv[c]*m;
      }
    }
  }
  __syncthreads();

  // post conv: out oi x 16 px, K=64; + bias + residual (vb = lb)
  float pres[16];
  {
    u64 pa[8];
    #pragma unroll
    for (int j=0;j<8;j++) pa[j]=0ull;
    for (int k=0; k<64; k++){
      const ulonglong2* xr = (const ulonglong2*)(xs + k*132 + px0);
      ulonglong2 x01 = xr[0], x23 = xr[1], x45 = xr[2], x67 = xr[3];
      u64 xv[8] = {x01.x,x01.y,x23.x,x23.y,x45.x,x45.y,x67.x,x67.y};
      float w = wb[k*64 + oi];
      u64 wp = pk2(w,w);
      #pragma unroll
      for (int j=0;j<8;j++) fma2(pa[j], wp, xv[j]);
    }
    float bb = __ldg(post_b + oi);
    const float* rr = vb + oi*132 + px0;
    #pragma unroll
    for (int j=0;j<8;j++){
      float2 v = upk2(pa[j]);
      pres[2*j]   = v.x + bb + rr[2*j];
      pres[2*j+1] = v.y + bb + rr[2*j+1];
    }
  }
  __syncthreads();
  {
    float* dst = xs + oi*132 + px0;
    #pragma unroll
    for (int j=0;j<8;j++) *((float2*)(dst + 2*j)) = make_float2(pres[2*j], pres[2*j+1]);
    const float* vp = g_vd + (size_t)b*64*HW + pb;
    for (int i=tid; i<64*32; i+=512){
      int ch=i>>5, q=i&31;
      ((float4*)(vb + ch*132))[q] = __ldg((const float4*)(vp + (size_t)ch*HW) + q);
    }
  }
  __syncthreads();

  // attn mix: out oi (head oi>>3), 16 px
  {
    int h = oi >> 3;
    u64 aa[8];
    #pragma unroll
    for (int j=0;j<8;j++) aa[j]=0ull;
    #pragma unroll
    for (int d=0;d<8;d++){
      float w = W_s[oi*8 + d];
      u64 wp = pk2(w,w);
      const ulonglong2* xr = (const ulonglong2*)(vb + (h*8+d)*132 + px0);
      ulonglong2 x01 = xr[0], x23 = xr[1], x45 = xr[2], x67 = xr[3];
      fma2(aa[0], wp, x01.x); fma2(aa[1], wp, x01.y);
      fma2(aa[2], wp, x23.x); fma2(aa[3], wp, x23.y);
      fma2(aa[4], wp, x45.x); fma2(aa[5], wp, x45.y);
      fma2(aa[6], wp, x67.x); fma2(aa[7], wp, x67.y);
    }
    __syncthreads();   // all vb reads done
    ulonglong2* dst = (ulonglong2*)(vb + oi*132 + px0);
    #pragma unroll
    for (int m=0;m<4;m++){ ulonglong2 v; v.x=aa[2*m]; v.y=aa[2*m+1]; dst[m]=v; }
    for (int i=tid; i<4096; i+=512) ((float4*)wb)[i] = ((const float4*)g_poutT)[i];
  }
  __syncthreads();

  // proj_out: outs (oi, oi+64) x 16 px, K=128 (k<64 -> vb=attn, k>=64 -> xs=post)
  {
    u64 po[2][8];
    #pragma unroll
    for (int i=0;i<2;i++){
      #pragma unroll
      for (int j=0;j<8;j++) po[i][j]=0ull;
    }
    for (int k=0; k<64; k++){
      const ulonglong2* xr = (const ulonglong2*)(vb + k*132 + px0);
      ulonglong2 x01 = xr[0], x23 = xr[1], x45 = xr[2], x67 = xr[3];
      u64 xv[8] = {x01.x,x01.y,x23.x,x23.y,x45.x,x45.y,x67.x,x67.y};
      const float* wrow = wb + k*128;
      #pragma unroll
      for (int i=0;i<2;i++){
        float w = wrow[oi + 64*i];
        u64 wp = pk2(w,w);
        #pragma unroll
        for (int j=0;j<8;j++) fma2(po[i][j], wp, xv[j]);
      }
    }
    for (int k=0; k<64; k++){
      const ulonglong2* xr = (const ulonglong2*)(xs + k*132 + px0);
      ulonglong2 x01 = xr[0], x23 = xr[1], x45 = xr[2], x67 = xr[3];
      u64 xv[8] = {x01.x,x01.y,x23.x,x23.y,x45.x,x45.y,x67.x,x67.y};
      const float* wrow = wb + (64+k)*128;
      #pragma unroll
      for (int i=0;i<2;i++){
        float w = wrow[oi + 64*i];
        u64 wp = pk2(w,w);
        #pragma unroll
        for (int j=0;j<8;j++) fma2(po[i][j], wp, xv[j]);
      }
    }
    __syncthreads();   // all vb/xs reads done
    ulonglong2* d0 = (ulonglong2*)(vb + oi*132 + px0);
    ulonglong2* d1 = (ulonglong2*)(xs + oi*132 + px0);
    #pragma unroll
    for (int m=0;m<4;m++){
      ulonglong2 v0; v0.x=po[0][2*m]; v0.y=po[0][2*m+1]; d0[m]=v0;
      ulonglong2 v1; v1.x=po[1][2*m]; v1.y=po[1][2*m+1]; d1[m]=v1;
    }
  }
  __syncthreads();
  {
    float* op = out + (size_t)b*128*HW + pb;
    for (int i=tid; i<64*32; i+=512){
      int ch=i>>5, q=i&31;
      *((float4*)(op + (size_t)ch*HW) + q)      = ((const float4*)(vb + ch*132))[q];
      *((float4*)(op + (size_t)(64+ch)*HW) + q) = ((const float4*)(xs + ch*132))[q];
    }
  }
}

// ------------------------------- launch -------------------------------
extern "C" void kernel_launch(void* const* d_in, const int* in_sizes, int n_in,
                              void* d_out, int out_size)
{
  const float* x      = (const float*)d_in[0];
  const float* projw  = (const float*)d_in[1];
  const float* prew   = (const float*)d_in[2];
  const float* preb   = (const float*)d_in[3];
  const float* w1     = (const float*)d_in[4];
  const float* b1     = (const float*)d_in[5];
  const float* w2     = (const float*)d_in[6];
  const float* b2     = (const float*)d_in[7];
  const float* sw     = (const float*)d_in[8];
  const float* sb     = (const float*)d_in[9];
  const float* postw  = (const float*)d_in[10];
  const float* postb  = (const float*)d_in[11];
  const float* qkvw   = (const float*)d_in[12];
  const float* dww    = (const float*)d_in[13];
  const float* gw1    = (const float*)d_in[14];
  const float* gb1    = (const float*)d_in[15];
  const float* gw2    = (const float*)d_in[16];
  const float* gb2    = (const float*)d_in[17];
  const float* temp   = (const float*)d_in[18];
  const float* scales = (const float*)d_in[19];
  const float* poutw  = (const float*)d_in[20];
  float* out = (float*)d_out;

  cudaFuncSetAttribute(k_front, cudaFuncAttributeMaxDynamicSharedMemorySize, FR_TOT*4);
  cudaFuncSetAttribute(k_gram,  cudaFuncAttributeMaxDynamicSharedMemorySize, GM_TOT*4);
  cudaFuncSetAttribute(k_final, cudaFuncAttributeMaxDynamicSharedMemorySize, FN_TOT*4);

  k_prep <<<64, 256>>>(projw, prew, qkvw, gw1, postw, poutw);
  k_front<<<2048, 256, FR_TOT*4>>>(x, preb, gb1, gw2, gb2);
  k_dw   <<<256*64, 256>>>(dww);
  k_small<<<1, 32>>>(w1, b1, w2, b2);
  k_thr  <<<256, 256>>>(sw, sb);
  k_gram <<<1024, 256, GM_TOT*4>>>(dww);
  k_attn <<<1, 32>>>(temp, scales);
  k_final<<<2048, 512, FN_TOT*4>>>(sw, sb, postb, out);
}